// round 10
// baseline (speedup 1.0000x reference)
#include <cuda_runtime.h>
#include <cuda_fp16.h>
#include <math.h>
#include <stdint.h>

#define B_   16

// ---- base-PTX helpers ----
__device__ __forceinline__ uint32_t smem_u32(const void* p) {
    uint32_t a;
    asm("{ .reg .u64 t; cvta.to.shared.u64 t, %1; cvt.u32.u64 %0, t; }" : "=r"(a) : "l"(p));
    return a;
}
#define LDSM4(r0, r1, r2, r3, addr) \
    asm volatile("ldmatrix.sync.aligned.m8n8.x4.shared.b16 {%0,%1,%2,%3}, [%4];" \
        : "=r"(r0), "=r"(r1), "=r"(r2), "=r"(r3) : "r"(addr))
__device__ __forceinline__ void mma16816(float* c, const uint32_t* a, const uint32_t* b) {
    asm volatile("mma.sync.aligned.m16n8k16.row.col.f32.f16.f16.f32 "
                 "{%0,%1,%2,%3}, {%4,%5,%6,%7}, {%8,%9}, {%0,%1,%2,%3};"
                 : "+f"(c[0]), "+f"(c[1]), "+f"(c[2]), "+f"(c[3])
                 : "r"(a[0]), "r"(a[1]), "r"(a[2]), "r"(a[3]), "r"(b[0]), "r"(b[1]));
}
__device__ __forceinline__ void cpa16(uint32_t dst, const void* src, uint32_t sz) {
    asm volatile("cp.async.cg.shared.global [%0], [%1], 16, %2;" :: "r"(dst), "l"(src), "r"(sz));
}
#define CP_COMMIT() asm volatile("cp.async.commit_group;")
#define CP_WAIT0()  asm volatile("cp.async.wait_group 0;")
#define CP_WAIT1()  asm volatile("cp.async.wait_group 1;")
#define CP_WAIT2()  asm volatile("cp.async.wait_group 2;")

// ---- scratch ----
__device__ float g_s1[B_ * 512];
__device__ float g_s2[B_ * 512];
__device__ float g_sr[B_ * 512];
__device__ float g_d[2][B_ * 512];
__device__ float g_A[2][512 * 512];
__device__ float g_wr3[3 * 512];
__device__ __half g_ydc[(size_t)B_ * 64 * 64 * 512];  // deconv out (pre-blur), fp16
__device__ __half g_a1[(size_t)B_ * 32 * 32 * 512];   // x*s1*wscale, fp16
__device__ __half g_a2[(size_t)B_ * 64 * 64 * 512];   // block1 out *s2*wscale, fp16
__device__ __half g_wh[(size_t)2 * 9 * 512 * 512];    // wT[conv][t][cout][cin] fp16

static __constant__ float kFclScale = 0.04419417382415922f;   // 1/sqrt(512)
#define WS9F 0.014731391274719738f                            // 1/sqrt(4608)

// taps: classes 0..3 = deconv parity (rh*2+rw), class 4 = conv2 3x3
struct TapList { int n; int dy[9]; int dx[9]; int wi[9]; };
__constant__ TapList c_taps[5] = {
    {4, {-1,-1, 0, 0, 0,0,0,0,0}, {-1, 0,-1, 0, 0,0,0,0,0}, {0,2,6,8, 0,0,0,0,0}},
    {2, {-1, 0, 0, 0, 0,0,0,0,0}, { 0, 0, 0, 0, 0,0,0,0,0}, {1,7, 0,0,0,0,0,0,0}},
    {2, { 0, 0, 0, 0, 0,0,0,0,0}, {-1, 0, 0, 0, 0,0,0,0,0}, {3,5, 0,0,0,0,0,0,0}},
    {1, { 0, 0, 0, 0, 0,0,0,0,0}, { 0, 0, 0, 0, 0,0,0,0,0}, {4, 0,0,0,0,0,0,0,0}},
    {9, {-1,-1,-1, 0, 0, 0, 1, 1, 1}, {-1, 0, 1,-1, 0, 1,-1, 0, 1}, {0,1,2,3,4,5,6,7,8}}
};
// {ymul, yadd, xmul, xadd}
__constant__ int4 c_geo[5] = { {2,0,2,0}, {2,0,2,1}, {2,1,2,0}, {2,1,2,1}, {1,0,1,0} };

// ---- small kernels ----
__global__ void fcl3_kernel(const float* __restrict__ w,
                            const float* __restrict__ fw1, const float* __restrict__ fb1, float* __restrict__ o1,
                            const float* __restrict__ fw2, const float* __restrict__ fb2, float* __restrict__ o2,
                            const float* __restrict__ fw3, const float* __restrict__ fb3, float* __restrict__ o3) {
    __shared__ float wsh[512];
    int b = blockIdx.x, c = threadIdx.x, sel = blockIdx.y;
    const float* fw = sel == 0 ? fw1 : (sel == 1 ? fw2 : fw3);
    const float* fb = sel == 0 ? fb1 : (sel == 1 ? fb2 : fb3);
    float* o = sel == 0 ? o1 : (sel == 1 ? o2 : o3);
    wsh[c] = w[b * 512 + c];
    __syncthreads();
    float acc = 0.f;
#pragma unroll 8
    for (int k = 0; k < 512; ++k) acc += wsh[k] * fw[k * 512 + c];
    o[b * 512 + c] = acc * kFclScale + fb[c];
}

__global__ void a_kernel(const float* __restrict__ w1, const float* __restrict__ w2) {
    int cin = blockIdx.x, sel = blockIdx.y, c = threadIdx.x;
    const float* w = sel ? w2 : w1;
    float acc = 0.f;
#pragma unroll
    for (int t = 0; t < 9; ++t) {
        float v = w[((size_t)t * 512 + cin) * 512 + c];
        acc += v * v;
    }
    g_A[sel][cin * 512 + c] = acc * (1.0f / 4608.0f);
}

__global__ void d_kernel() {
    __shared__ float ssq[512];
    int b = blockIdx.x, sel = blockIdx.y, c = threadIdx.x;
    const float* s = sel ? g_s2 : g_s1;
    float sv = s[b * 512 + c];
    ssq[c] = sv * sv;
    __syncthreads();
    float acc = 0.f;
#pragma unroll 8
    for (int k = 0; k < 512; ++k) acc += g_A[sel][k * 512 + c] * ssq[k];
    g_d[sel][b * 512 + c] = rsqrtf(acc + 1e-8f);
}

__global__ void wr3_kernel(const float* __restrict__ wr) {
    int c = threadIdx.x;
#pragma unroll
    for (int j = 0; j < 3; ++j) g_wr3[j * 512 + c] = wr[c * 3 + j] * kFclScale;
}

// A1 = fp16(x * s1 * wscale)
__global__ void prep_a1(const float* __restrict__ x) {
    int idx = blockIdx.x * 256 + threadIdx.x;  // float4 units
    float4 v = ((const float4*)x)[idx];
    int b = idx >> 17, c4 = idx & 127;
    float4 s = ((const float4*)g_s1)[b * 128 + c4];
    __half2 h0 = __floats2half2_rn(v.x * s.x * WS9F, v.y * s.y * WS9F);
    __half2 h1 = __floats2half2_rn(v.z * s.z * WS9F, v.w * s.w * WS9F);
    ((__half2*)g_a1)[idx * 2] = h0;
    ((__half2*)g_a1)[idx * 2 + 1] = h1;
}

// wT[conv][t][cout][cin] = fp16(transpose(conv_w[t]))
__global__ void wprep_kernel(const float* __restrict__ w1, const float* __restrict__ w2) {
    __shared__ float tile[32][33];
    int tz = blockIdx.z, conv = tz / 9, t = tz % 9;
    const float* w = conv ? w2 : w1;
    __half* dh = g_wh + (size_t)conv * 9 * 512 * 512;
    int ci0 = blockIdx.x * 32, co0 = blockIdx.y * 32;
    int tx = threadIdx.x & 31, ty = threadIdx.x >> 5;
#pragma unroll
    for (int r = 0; r < 4; ++r)
        tile[ty + r * 8][tx] = w[(((size_t)t * 512 + ci0 + ty + r * 8) << 9) + co0 + tx];
    __syncthreads();
#pragma unroll
    for (int r = 0; r < 4; ++r) {
        int co = co0 + ty + r * 8;
        dh[(((size_t)t * 512 + co) << 9) + ci0 + tx] = __float2half_rn(tile[tx][ty + r * 8]);
    }
}

// ---- HMMA implicit-GEMM conv: CTA 256px x 128cout, 16 warps (8M x 2N), K-stage 64 ----
#define ASTAGE 36864         // 256 rows * 144B
#define STAGE  55296         // A + B(128 rows * 144B)
#define SMEMSZ (3 * STAGE)   // 165888, 1 CTA/SM (16 warps)

__global__ __launch_bounds__(512, 1)
void mma_conv_kernel(const __half* __restrict__ xin, int Hin, int Win,
                     const __half* __restrict__ wh,
                     int tapsBase, int tilesPerImg, int pxs, int pxm,
                     float* __restrict__ outf, __half* __restrict__ outh,
                     const float* __restrict__ dvec, const float* __restrict__ noise,
                     const float* __restrict__ snoise, const float* __restrict__ bias) {
    extern __shared__ __align__(16) char smem[];
    const uint32_t su = smem_u32(smem);
    const int tid = threadIdx.x, lane = tid & 31, wid = tid >> 5;
    const int sel = tapsBase + blockIdx.z;
    const int b = blockIdx.y / tilesPerImg;
    const int a0 = (blockIdx.y % tilesPerImg) * (256 >> pxs);
    const int cout0 = blockIdx.x * 128;
    const int m0 = (wid & 7) * 32, n0 = (wid >> 3) * 64;

    float acc[2][8][4];
#pragma unroll
    for (int i = 0; i < 2; ++i)
#pragma unroll
        for (int j = 0; j < 8; ++j)
#pragma unroll
            for (int k = 0; k < 4; ++k) acc[i][j][k] = 0.f;

    const int S = c_taps[sel].n * 8;

    auto load_stage = [&](int st, int p) {
        int t = st >> 3, ck = (st & 7) << 6;
        uint32_t base = su + p * STAGE;
        int dy = c_taps[sel].dy[t], dx = c_taps[sel].dx[t];
#pragma unroll
        for (int i = 0; i < 4; ++i) {   // A: 256 rows x 64 fp16
            int id = tid + i * 512;
            int r = id >> 3, seg = id & 7;
            int iy = a0 + (r >> pxs) + dy, ix = (r & pxm) + dx;
            bool ok = ((unsigned)iy < (unsigned)Hin) && ((unsigned)ix < (unsigned)Win);
            const void* src = xin + ((((size_t)b * Hin + (ok ? iy : 0)) * Win + (ok ? ix : 0)) << 9)
                              + ck + (seg << 3);
            cpa16(base + r * 144 + seg * 16, src, ok ? 16u : 0u);
        }
        const __half* wt = wh + (((size_t)(c_taps[sel].wi[t] * 512 + cout0)) << 9) + ck;
#pragma unroll
        for (int i = 0; i < 2; ++i) {   // B: 128 rows x 64 fp16
            int id = tid + i * 512;
            int row = id >> 3, seg = id & 7;
            cpa16(base + ASTAGE + row * 144 + seg * 16, wt + ((size_t)row << 9) + (seg << 3), 16u);
        }
    };

    auto compute = [&](int p) {
        uint32_t Ab = su + p * STAGE;
        uint32_t Bb = Ab + ASTAGE;
#pragma unroll
        for (int kk = 0; kk < 64; kk += 16) {
            uint32_t a[2][4];
#pragma unroll
            for (int mi = 0; mi < 2; ++mi) {
                uint32_t addr = Ab + (m0 + mi * 16 + (lane & 15)) * 144
                                + (kk + ((lane >> 4) << 3)) * 2;
                LDSM4(a[mi][0], a[mi][1], a[mi][2], a[mi][3], addr);
            }
            uint32_t bb[8][2];
#pragma unroll
            for (int ng = 0; ng < 4; ++ng) {
                int row = n0 + ng * 16 + (lane & 7) + ((lane >> 4) << 3);
                uint32_t addr = Bb + row * 144 + (kk + (((lane >> 3) & 1) << 3)) * 2;
                uint32_t r0, r1, r2, r3;
                LDSM4(r0, r1, r2, r3, addr);
                bb[ng * 2][0] = r0;     bb[ng * 2][1] = r1;
                bb[ng * 2 + 1][0] = r2; bb[ng * 2 + 1][1] = r3;
            }
#pragma unroll
            for (int mi = 0; mi < 2; ++mi)
#pragma unroll
                for (int ni = 0; ni < 8; ++ni)
                    mma16816(acc[mi][ni], a[mi], bb[ni]);
        }
    };

    load_stage(0, 0); CP_COMMIT();
    load_stage(1, 1); CP_COMMIT();
    for (int st = 0; st < S; ++st) {
        int nxt = st + 2;
        if (nxt < S) { load_stage(nxt, nxt % 3); CP_COMMIT(); CP_WAIT2(); }
        else if (st + 1 < S) { CP_WAIT1(); }
        else { CP_WAIT0(); }
        __syncthreads();
        compute(st % 3);
        __syncthreads();
    }

    // epilogue
    const int4 geo = c_geo[sel];
    const int quad = lane >> 2, tq = lane & 3;
    if (dvec) {
        float2 dv2[8], sn2[8], bi2[8];
#pragma unroll
        for (int ni = 0; ni < 8; ++ni) {
            int col = cout0 + n0 + ni * 8 + tq * 2;
            dv2[ni] = *(const float2*)(dvec + b * 512 + col);
            sn2[ni] = *(const float2*)(snoise + col);
            bi2[ni] = *(const float2*)(bias + col);
        }
#pragma unroll
        for (int mi = 0; mi < 2; ++mi)
#pragma unroll
            for (int h = 0; h < 2; ++h) {
                int r = m0 + mi * 16 + quad + h * 8;
                int oy = (a0 + (r >> pxs)) * geo.x + geo.y;
                int ox = (r & pxm) * geo.z + geo.w;
                size_t pbase = (((size_t)b * 64 + oy) * 64 + ox) << 9;
                float nz = noise[(((size_t)b * 64 + oy) << 6) + ox];
#pragma unroll
                for (int ni = 0; ni < 8; ++ni) {
                    float c0 = acc[mi][ni][h * 2], c1 = acc[mi][ni][h * 2 + 1];
                    float2 v;
                    v.x = c0 * dv2[ni].x + sn2[ni].x * nz + bi2[ni].x;
                    v.y = c1 * dv2[ni].y + sn2[ni].y * nz + bi2[ni].y;
                    v.x = v.x >= 0.f ? v.x : 0.2f * v.x;
                    v.y = v.y >= 0.f ? v.y : 0.2f * v.y;
                    *(float2*)(outf + pbase + cout0 + n0 + ni * 8 + tq * 2) = v;
                }
            }
    } else {
#pragma unroll
        for (int mi = 0; mi < 2; ++mi)
#pragma unroll
            for (int h = 0; h < 2; ++h) {
                int r = m0 + mi * 16 + quad + h * 8;
                int oy = (a0 + (r >> pxs)) * geo.x + geo.y;
                int ox = (r & pxm) * geo.z + geo.w;
                size_t pbase = (((size_t)b * 64 + oy) * 64 + ox) << 9;
#pragma unroll
                for (int ni = 0; ni < 8; ++ni) {
                    __half2 v = __floats2half2_rn(acc[mi][ni][h * 2], acc[mi][ni][h * 2 + 1]);
                    *(__half2*)(outh + pbase + cout0 + n0 + ni * 8 + tq * 2) = v;
                }
            }
    }
}

// ---- blur (fp16 in) + demod1 + noise + bias + lrelu -> fp16 (v*s2*wscale) ----
__global__ void blur_kernel(const __half* __restrict__ ydc, __half* __restrict__ xout,
                            const float* __restrict__ noise, const float* __restrict__ snoise,
                            const float* __restrict__ bias) {
    const int cg = threadIdx.x & 127, c = cg * 4;
    const int xi = (blockIdx.x % 32) * 2 + (threadIdx.x >> 7);
    const int b = blockIdx.x / 32;
    const float F[4] = {0.25f, 0.75f, 0.75f, 0.25f};

    float4 dvv = *(const float4*)(&g_d[0][b * 512 + c]);
    float4 snv = *(const float4*)(snoise + c);
    float4 biv = *(const float4*)(bias + c);
    float4 s2v = *(const float4*)(&g_s2[b * 512 + c]);

    auto hrow = [&](int v) -> float4 {
        float4 r = make_float4(0.f, 0.f, 0.f, 0.f);
        if (v < 0 || v >= 64) return r;
        const __half* base = ydc + (((size_t)b * 64 + v) * 64) * 512 + c;
#pragma unroll
        for (int u = 0; u < 4; ++u) {
            int xx = xi + u - 1;
            if (xx >= 0 && xx < 64) {
                const __half2* p = (const __half2*)(base + (size_t)xx * 512);
                float2 t0 = __half22float2(p[0]);
                float2 t1 = __half22float2(p[1]);
                r.x += F[u] * t0.x; r.y += F[u] * t0.y; r.z += F[u] * t1.x; r.w += F[u] * t1.y;
            }
        }
        return r;
    };

    float4 h0 = make_float4(0.f, 0.f, 0.f, 0.f);
    float4 h1 = hrow(0), h2 = hrow(1);
    for (int y = 0; y < 64; ++y) {
        float4 h3 = hrow(y + 2);
        float4 o;
        o.x = 0.25f * h0.x + 0.75f * h1.x + 0.75f * h2.x + 0.25f * h3.x;
        o.y = 0.25f * h0.y + 0.75f * h1.y + 0.75f * h2.y + 0.25f * h3.y;
        o.z = 0.25f * h0.z + 0.75f * h1.z + 0.75f * h2.z + 0.25f * h3.z;
        o.w = 0.25f * h0.w + 0.75f * h1.w + 0.75f * h2.w + 0.25f * h3.w;
        float nz = noise[((size_t)b * 64 + y) * 64 + xi];
        float4 v;
        v.x = o.x * dvv.x + snv.x * nz + biv.x;
        v.y = o.y * dvv.y + snv.y * nz + biv.y;
        v.z = o.z * dvv.z + snv.z * nz + biv.z;
        v.w = o.w * dvv.w + snv.w * nz + biv.w;
        v.x = v.x >= 0.f ? v.x : 0.2f * v.x;
        v.y = v.y >= 0.f ? v.y : 0.2f * v.y;
        v.z = v.z >= 0.f ? v.z : 0.2f * v.z;
        v.w = v.w >= 0.f ? v.w : 0.2f * v.w;
        size_t off = (((size_t)b * 64 + y) * 64 + xi) * 512 + c;
        __half2 p0 = __floats2half2_rn(v.x * s2v.x * WS9F, v.y * s2v.y * WS9F);
        __half2 p1 = __floats2half2_rn(v.z * s2v.z * WS9F, v.w * s2v.w * WS9F);
        ((__half2*)(xout + off))[0] = p0;
        ((__half2*)(xout + off))[1] = p1;
        h0 = h1; h1 = h2; h2 = h3;
    }
}

// ---- toRGB ----
__global__ void torgb_kernel(const float* __restrict__ x2, float* __restrict__ rgb,
                             const float* __restrict__ biasr) {
    const int warp = threadIdx.x >> 5, lane = threadIdx.x & 31;
    const int pix = blockIdx.x * 8 + warp;
    const int b = pix >> 12;
    const float* xp = x2 + (size_t)pix * 512;
    const float* sp = g_sr + b * 512;
    float r0 = 0.f, r1 = 0.f, r2 = 0.f;
#pragma unroll
    for (int k = 0; k < 4; ++k) {
        int c = lane * 4 + k * 128;
        float4 xv = *(const float4*)(xp + c);
        float4 sv = *(const float4*)(sp + c);
        xv.x *= sv.x; xv.y *= sv.y; xv.z *= sv.z; xv.w *= sv.w;
        float4 w0 = *(const float4*)(g_wr3 + 0 * 512 + c);
        float4 w1 = *(const float4*)(g_wr3 + 1 * 512 + c);
        float4 w2 = *(const float4*)(g_wr3 + 2 * 512 + c);
        r0 += xv.x * w0.x + xv.y * w0.y + xv.z * w0.z + xv.w * w0.w;
        r1 += xv.x * w1.x + xv.y * w1.y + xv.z * w1.z + xv.w * w1.w;
        r2 += xv.x * w2.x + xv.y * w2.y + xv.z * w2.z + xv.w * w2.w;
    }
#pragma unroll
    for (int off = 16; off > 0; off >>= 1) {
        r0 += __shfl_xor_sync(0xffffffffu, r0, off);
        r1 += __shfl_xor_sync(0xffffffffu, r1, off);
        r2 += __shfl_xor_sync(0xffffffffu, r2, off);
    }
    if (lane == 0) {
        float v0 = r0 + biasr[0], v1 = r1 + biasr[1], v2 = r2 + biasr[2];
        rgb[(size_t)pix * 3 + 0] = v0 >= 0.f ? v0 : 0.2f * v0;
        rgb[(size_t)pix * 3 + 1] = v1 >= 0.f ? v1 : 0.2f * v1;
        rgb[(size_t)pix * 3 + 2] = v2 >= 0.f ? v2 : 0.2f * v2;
    }
}

// ---- launch ----
extern "C" void kernel_launch(void* const* d_in, const int* in_sizes, int n_in,
                              void* d_out, int out_size) {
    const float* x       = (const float*)d_in[0];
    const float* w       = (const float*)d_in[1];
    const float* noise1  = (const float*)d_in[2];
    const float* noise2  = (const float*)d_in[3];
    const float* fcl1_w  = (const float*)d_in[4];
    const float* fcl1_b  = (const float*)d_in[5];
    const float* conv1_w = (const float*)d_in[6];
    const float* sn1     = (const float*)d_in[7];
    const float* bias1   = (const float*)d_in[8];
    const float* fcl2_w  = (const float*)d_in[9];
    const float* fcl2_b  = (const float*)d_in[10];
    const float* conv2_w = (const float*)d_in[11];
    const float* sn2     = (const float*)d_in[12];
    const float* bias2   = (const float*)d_in[13];
    const float* fclr_w  = (const float*)d_in[14];
    const float* fclr_b  = (const float*)d_in[15];
    const float* convr_w = (const float*)d_in[16];
    const float* biasr   = (const float*)d_in[17];

    float* x2out  = (float*)d_out;
    float* rgbout = x2out + (size_t)B_ * 64 * 64 * 512;

    float *s1, *s2, *sr, *dd;
    __half *ydc, *a1, *a2, *wh;
    cudaGetSymbolAddress((void**)&s1, g_s1);
    cudaGetSymbolAddress((void**)&s2, g_s2);
    cudaGetSymbolAddress((void**)&sr, g_sr);
    cudaGetSymbolAddress((void**)&dd, g_d);
    cudaGetSymbolAddress((void**)&ydc, g_ydc);
    cudaGetSymbolAddress((void**)&a1, g_a1);
    cudaGetSymbolAddress((void**)&a2, g_a2);
    cudaGetSymbolAddress((void**)&wh, g_wh);
    float* d2 = dd + B_ * 512;

    cudaFuncSetAttribute(mma_conv_kernel, cudaFuncAttributeMaxDynamicSharedMemorySize, SMEMSZ);

    fcl3_kernel<<<dim3(B_, 3), 512>>>(w, fcl1_w, fcl1_b, s1, fcl2_w, fcl2_b, s2,
                                      fclr_w, fclr_b, sr);
    a_kernel<<<dim3(512, 2), 512>>>(conv1_w, conv2_w);
    d_kernel<<<dim3(B_, 2), 512>>>();
    wr3_kernel<<<1, 512>>>(convr_w);
    prep_a1<<<8192, 256>>>(x);
    wprep_kernel<<<dim3(16, 16, 18), 256>>>(conv1_w, conv2_w);

    // deconv: 4 parity classes in ONE launch (grid.z = class), M=256 input-px tiles
    mma_conv_kernel<<<dim3(4, B_ * 4, 4), 512, SMEMSZ>>>(
        a1, 32, 32, wh, /*tapsBase=*/0, /*tilesPerImg=*/4, /*pxs=*/5, /*pxm=*/31,
        nullptr, ydc, nullptr, nullptr, nullptr, nullptr);

    blur_kernel<<<B_ * 32, 256>>>(ydc, a2, noise1, sn1, bias1);

    // conv2: 3x3 SAME, fused demod/noise/bias/lrelu -> d_out, M=256 px tiles
    mma_conv_kernel<<<dim3(4, B_ * 16, 1), 512, SMEMSZ>>>(
        a2, 64, 64, wh + (size_t)9 * 512 * 512, /*tapsBase=*/4, /*tilesPerImg=*/16,
        /*pxs=*/6, /*pxm=*/63,
        x2out, nullptr, d2, noise2, sn2, bias2);

    torgb_kernel<<<(B_ * 64 * 64) / 8, 256>>>(x2out, rgbout, biasr);
}

// round 11
// speedup vs baseline: 1.1379x; 1.1379x over previous
#include <cuda_runtime.h>
#include <cuda_fp16.h>
#include <math.h>
#include <stdint.h>

#define B_   16

// ---- base-PTX helpers ----
__device__ __forceinline__ uint32_t smem_u32(const void* p) {
    uint32_t a;
    asm("{ .reg .u64 t; cvta.to.shared.u64 t, %1; cvt.u32.u64 %0, t; }" : "=r"(a) : "l"(p));
    return a;
}
#define LDSM4(r0, r1, r2, r3, addr) \
    asm volatile("ldmatrix.sync.aligned.m8n8.x4.shared.b16 {%0,%1,%2,%3}, [%4];" \
        : "=r"(r0), "=r"(r1), "=r"(r2), "=r"(r3) : "r"(addr))
__device__ __forceinline__ void mma16816(float* c, const uint32_t* a, const uint32_t* b) {
    asm volatile("mma.sync.aligned.m16n8k16.row.col.f32.f16.f16.f32 "
                 "{%0,%1,%2,%3}, {%4,%5,%6,%7}, {%8,%9}, {%0,%1,%2,%3};"
                 : "+f"(c[0]), "+f"(c[1]), "+f"(c[2]), "+f"(c[3])
                 : "r"(a[0]), "r"(a[1]), "r"(a[2]), "r"(a[3]), "r"(b[0]), "r"(b[1]));
}
__device__ __forceinline__ void cpa16(uint32_t dst, const void* src, uint32_t sz) {
    asm volatile("cp.async.cg.shared.global [%0], [%1], 16, %2;" :: "r"(dst), "l"(src), "r"(sz));
}
#define CP_COMMIT() asm volatile("cp.async.commit_group;")
#define CP_WAIT0()  asm volatile("cp.async.wait_group 0;")
#define CP_WAIT1()  asm volatile("cp.async.wait_group 1;")
#define CP_WAIT2()  asm volatile("cp.async.wait_group 2;")

// ---- scratch ----
__device__ float g_s1[B_ * 512];
__device__ float g_s2[B_ * 512];
__device__ float g_sr[B_ * 512];
__device__ float g_d[2][B_ * 512];
__device__ float g_A[2][512 * 512];
__device__ float g_wr3[3 * 512];
__device__ __half g_ydc[(size_t)B_ * 64 * 64 * 512];  // deconv out (pre-blur), fp16
__device__ __half g_a1[(size_t)B_ * 32 * 32 * 512];   // x*s1*wscale, fp16
__device__ __half g_a2[(size_t)B_ * 64 * 64 * 512];   // block1 out *s2*wscale, fp16
__device__ __half g_wh[(size_t)2 * 9 * 512 * 512];    // wT[conv][t][cout][cin] fp16

static __constant__ float kFclScale = 0.04419417382415922f;   // 1/sqrt(512)
#define WS9F 0.014731391274719738f                            // 1/sqrt(4608)

// taps: classes 0..3 = deconv parity (rh*2+rw), class 4 = conv2 3x3
struct TapList { int n; int dy[9]; int dx[9]; int wi[9]; };
__constant__ TapList c_taps[5] = {
    {4, {-1,-1, 0, 0, 0,0,0,0,0}, {-1, 0,-1, 0, 0,0,0,0,0}, {0,2,6,8, 0,0,0,0,0}},
    {2, {-1, 0, 0, 0, 0,0,0,0,0}, { 0, 0, 0, 0, 0,0,0,0,0}, {1,7, 0,0,0,0,0,0,0}},
    {2, { 0, 0, 0, 0, 0,0,0,0,0}, {-1, 0, 0, 0, 0,0,0,0,0}, {3,5, 0,0,0,0,0,0,0}},
    {1, { 0, 0, 0, 0, 0,0,0,0,0}, { 0, 0, 0, 0, 0,0,0,0,0}, {4, 0,0,0,0,0,0,0,0}},
    {9, {-1,-1,-1, 0, 0, 0, 1, 1, 1}, {-1, 0, 1,-1, 0, 1,-1, 0, 1}, {0,1,2,3,4,5,6,7,8}}
};
// {ymul, yadd, xmul, xadd}
__constant__ int4 c_geo[5] = { {2,0,2,0}, {2,0,2,1}, {2,1,2,0}, {2,1,2,1}, {1,0,1,0} };

// ---- small kernels ----
__global__ void fcl3_kernel(const float* __restrict__ w,
                            const float* __restrict__ fw1, const float* __restrict__ fb1, float* __restrict__ o1,
                            const float* __restrict__ fw2, const float* __restrict__ fb2, float* __restrict__ o2,
                            const float* __restrict__ fw3, const float* __restrict__ fb3, float* __restrict__ o3) {
    __shared__ float wsh[512];
    int b = blockIdx.x, c = threadIdx.x, sel = blockIdx.y;
    const float* fw = sel == 0 ? fw1 : (sel == 1 ? fw2 : fw3);
    const float* fb = sel == 0 ? fb1 : (sel == 1 ? fb2 : fb3);
    float* o = sel == 0 ? o1 : (sel == 1 ? o2 : o3);
    wsh[c] = w[b * 512 + c];
    __syncthreads();
    float acc = 0.f;
#pragma unroll 8
    for (int k = 0; k < 512; ++k) acc += wsh[k] * fw[k * 512 + c];
    o[b * 512 + c] = acc * kFclScale + fb[c];
}

__global__ void a_kernel(const float* __restrict__ w1, const float* __restrict__ w2) {
    int cin = blockIdx.x, sel = blockIdx.y, c = threadIdx.x;
    const float* w = sel ? w2 : w1;
    float acc = 0.f;
#pragma unroll
    for (int t = 0; t < 9; ++t) {
        float v = w[((size_t)t * 512 + cin) * 512 + c];
        acc += v * v;
    }
    g_A[sel][cin * 512 + c] = acc * (1.0f / 4608.0f);
}

__global__ void d_kernel() {
    __shared__ float ssq[512];
    int b = blockIdx.x, sel = blockIdx.y, c = threadIdx.x;
    const float* s = sel ? g_s2 : g_s1;
    float sv = s[b * 512 + c];
    ssq[c] = sv * sv;
    __syncthreads();
    float acc = 0.f;
#pragma unroll 8
    for (int k = 0; k < 512; ++k) acc += g_A[sel][k * 512 + c] * ssq[k];
    g_d[sel][b * 512 + c] = rsqrtf(acc + 1e-8f);
}

__global__ void wr3_kernel(const float* __restrict__ wr) {
    int c = threadIdx.x;
#pragma unroll
    for (int j = 0; j < 3; ++j) g_wr3[j * 512 + c] = wr[c * 3 + j] * kFclScale;
}

// A1 = fp16(x * s1 * wscale)
__global__ void prep_a1(const float* __restrict__ x) {
    int idx = blockIdx.x * 256 + threadIdx.x;  // float4 units
    float4 v = ((const float4*)x)[idx];
    int b = idx >> 17, c4 = idx & 127;
    float4 s = ((const float4*)g_s1)[b * 128 + c4];
    __half2 h0 = __floats2half2_rn(v.x * s.x * WS9F, v.y * s.y * WS9F);
    __half2 h1 = __floats2half2_rn(v.z * s.z * WS9F, v.w * s.w * WS9F);
    ((__half2*)g_a1)[idx * 2] = h0;
    ((__half2*)g_a1)[idx * 2 + 1] = h1;
}

// wT[conv][t][cout][cin] = fp16(transpose(conv_w[t]))
__global__ void wprep_kernel(const float* __restrict__ w1, const float* __restrict__ w2) {
    __shared__ float tile[32][33];
    int tz = blockIdx.z, conv = tz / 9, t = tz % 9;
    const float* w = conv ? w2 : w1;
    __half* dh = g_wh + (size_t)conv * 9 * 512 * 512;
    int ci0 = blockIdx.x * 32, co0 = blockIdx.y * 32;
    int tx = threadIdx.x & 31, ty = threadIdx.x >> 5;
#pragma unroll
    for (int r = 0; r < 4; ++r)
        tile[ty + r * 8][tx] = w[(((size_t)t * 512 + ci0 + ty + r * 8) << 9) + co0 + tx];
    __syncthreads();
#pragma unroll
    for (int r = 0; r < 4; ++r) {
        int co = co0 + ty + r * 8;
        dh[(((size_t)t * 512 + co) << 9) + ci0 + tx] = __float2half_rn(tile[tx][ty + r * 8]);
    }
}

// ---- HMMA implicit-GEMM conv: CTA 128px x 128cout, 8 warps (4M x 2N), K-stage 64 ----
#define ASTAGE 18432         // 128 rows * 144B
#define STAGE  36864         // A + B(128 rows * 144B)
#define SMEMSZ (3 * STAGE)   // 110592 -> 2 CTAs/SM

__global__ __launch_bounds__(256, 2)
void mma_conv_kernel(const __half* __restrict__ xin, int Hin, int Win,
                     const __half* __restrict__ wh,
                     int tapsBase, int tilesPerImg, int pxs, int pxm,
                     float* __restrict__ outf, __half* __restrict__ outh,
                     const float* __restrict__ dvec, const float* __restrict__ noise,
                     const float* __restrict__ snoise, const float* __restrict__ bias) {
    extern __shared__ __align__(16) char smem[];
    const uint32_t su = smem_u32(smem);
    const int tid = threadIdx.x, lane = tid & 31, wid = tid >> 5;
    const int sel = tapsBase + blockIdx.z;
    const int b = blockIdx.y / tilesPerImg;
    const int a0 = (blockIdx.y % tilesPerImg) * (128 >> pxs);
    const int cout0 = blockIdx.x * 128;
    const int m0 = (wid & 3) * 32, n0 = (wid >> 2) * 64;

    float acc[2][8][4];
#pragma unroll
    for (int i = 0; i < 2; ++i)
#pragma unroll
        for (int j = 0; j < 8; ++j)
#pragma unroll
            for (int k = 0; k < 4; ++k) acc[i][j][k] = 0.f;

    const int S = c_taps[sel].n * 8;

    auto load_stage = [&](int st, int p) {
        int t = st >> 3, ck = (st & 7) << 6;
        uint32_t base = su + p * STAGE;
        int dy = c_taps[sel].dy[t], dx = c_taps[sel].dx[t];
#pragma unroll
        for (int i = 0; i < 4; ++i) {   // A: 128 rows x 64 fp16
            int id = tid + i * 256;
            int r = id >> 3, seg = id & 7;
            int iy = a0 + (r >> pxs) + dy, ix = (r & pxm) + dx;
            bool ok = ((unsigned)iy < (unsigned)Hin) && ((unsigned)ix < (unsigned)Win);
            const void* src = xin + ((((size_t)b * Hin + (ok ? iy : 0)) * Win + (ok ? ix : 0)) << 9)
                              + ck + (seg << 3);
            cpa16(base + r * 144 + seg * 16, src, ok ? 16u : 0u);
        }
        const __half* wt = wh + (((size_t)(c_taps[sel].wi[t] * 512 + cout0)) << 9) + ck;
#pragma unroll
        for (int i = 0; i < 4; ++i) {   // B: 128 rows x 64 fp16
            int id = tid + i * 256;
            int row = id >> 3, seg = id & 7;
            cpa16(base + ASTAGE + row * 144 + seg * 16, wt + ((size_t)row << 9) + (seg << 3), 16u);
        }
    };

    auto compute = [&](int p) {
        uint32_t Ab = su + p * STAGE;
        uint32_t Bb = Ab + ASTAGE;
#pragma unroll
        for (int kk = 0; kk < 64; kk += 16) {
            uint32_t a[2][4];
#pragma unroll
            for (int mi = 0; mi < 2; ++mi) {
                uint32_t addr = Ab + (m0 + mi * 16 + (lane & 15)) * 144
                                + (kk + ((lane >> 4) << 3)) * 2;
                LDSM4(a[mi][0], a[mi][1], a[mi][2], a[mi][3], addr);
            }
            uint32_t bb[8][2];
#pragma unroll
            for (int ng = 0; ng < 4; ++ng) {
                int row = n0 + ng * 16 + (lane & 7) + ((lane >> 4) << 3);
                uint32_t addr = Bb + row * 144 + (kk + (((lane >> 3) & 1) << 3)) * 2;
                uint32_t r0, r1, r2, r3;
                LDSM4(r0, r1, r2, r3, addr);
                bb[ng * 2][0] = r0;     bb[ng * 2][1] = r1;
                bb[ng * 2 + 1][0] = r2; bb[ng * 2 + 1][1] = r3;
            }
#pragma unroll
            for (int mi = 0; mi < 2; ++mi)
#pragma unroll
                for (int ni = 0; ni < 8; ++ni)
                    mma16816(acc[mi][ni], a[mi], bb[ni]);
        }
    };

    load_stage(0, 0); CP_COMMIT();
    load_stage(1, 1); CP_COMMIT();
    for (int st = 0; st < S; ++st) {
        int nxt = st + 2;
        if (nxt < S) { load_stage(nxt, nxt % 3); CP_COMMIT(); CP_WAIT2(); }
        else if (st + 1 < S) { CP_WAIT1(); }
        else { CP_WAIT0(); }
        __syncthreads();
        compute(st % 3);
        __syncthreads();
    }

    // epilogue
    const int4 geo = c_geo[sel];
    const int quad = lane >> 2, tq = lane & 3;
    if (dvec) {
        float2 dv2[8], sn2[8], bi2[8];
#pragma unroll
        for (int ni = 0; ni < 8; ++ni) {
            int col = cout0 + n0 + ni * 8 + tq * 2;
            dv2[ni] = *(const float2*)(dvec + b * 512 + col);
            sn2[ni] = *(const float2*)(snoise + col);
            bi2[ni] = *(const float2*)(bias + col);
        }
#pragma unroll
        for (int mi = 0; mi < 2; ++mi)
#pragma unroll
            for (int h = 0; h < 2; ++h) {
                int r = m0 + mi * 16 + quad + h * 8;
                int oy = (a0 + (r >> pxs)) * geo.x + geo.y;
                int ox = (r & pxm) * geo.z + geo.w;
                size_t pbase = (((size_t)b * 64 + oy) * 64 + ox) << 9;
                float nz = noise[(((size_t)b * 64 + oy) << 6) + ox];
#pragma unroll
                for (int ni = 0; ni < 8; ++ni) {
                    float c0 = acc[mi][ni][h * 2], c1 = acc[mi][ni][h * 2 + 1];
                    float2 v;
                    v.x = c0 * dv2[ni].x + sn2[ni].x * nz + bi2[ni].x;
                    v.y = c1 * dv2[ni].y + sn2[ni].y * nz + bi2[ni].y;
                    v.x = v.x >= 0.f ? v.x : 0.2f * v.x;
                    v.y = v.y >= 0.f ? v.y : 0.2f * v.y;
                    *(float2*)(outf + pbase + cout0 + n0 + ni * 8 + tq * 2) = v;
                }
            }
    } else {
#pragma unroll
        for (int mi = 0; mi < 2; ++mi)
#pragma unroll
            for (int h = 0; h < 2; ++h) {
                int r = m0 + mi * 16 + quad + h * 8;
                int oy = (a0 + (r >> pxs)) * geo.x + geo.y;
                int ox = (r & pxm) * geo.z + geo.w;
                size_t pbase = (((size_t)b * 64 + oy) * 64 + ox) << 9;
#pragma unroll
                for (int ni = 0; ni < 8; ++ni) {
                    __half2 v = __floats2half2_rn(acc[mi][ni][h * 2], acc[mi][ni][h * 2 + 1]);
                    *(__half2*)(outh + pbase + cout0 + n0 + ni * 8 + tq * 2) = v;
                }
            }
    }
}

// ---- blur (fp16 in) + demod1 + noise + bias + lrelu -> fp16 (v*s2*wscale) ----
__global__ void blur_kernel(const __half* __restrict__ ydc, __half* __restrict__ xout,
                            const float* __restrict__ noise, const float* __restrict__ snoise,
                            const float* __restrict__ bias) {
    const int cg = threadIdx.x & 127, c = cg * 4;
    const int xi = (blockIdx.x % 32) * 2 + (threadIdx.x >> 7);
    const int b = blockIdx.x / 32;
    const float F[4] = {0.25f, 0.75f, 0.75f, 0.25f};

    float4 dvv = *(const float4*)(&g_d[0][b * 512 + c]);
    float4 snv = *(const float4*)(snoise + c);
    float4 biv = *(const float4*)(bias + c);
    float4 s2v = *(const float4*)(&g_s2[b * 512 + c]);

    auto hrow = [&](int v) -> float4 {
        float4 r = make_float4(0.f, 0.f, 0.f, 0.f);
        if (v < 0 || v >= 64) return r;
        const __half* base = ydc + (((size_t)b * 64 + v) * 64) * 512 + c;
#pragma unroll
        for (int u = 0; u < 4; ++u) {
            int xx = xi + u - 1;
            if (xx >= 0 && xx < 64) {
                const __half2* p = (const __half2*)(base + (size_t)xx * 512);
                float2 t0 = __half22float2(p[0]);
                float2 t1 = __half22float2(p[1]);
                r.x += F[u] * t0.x; r.y += F[u] * t0.y; r.z += F[u] * t1.x; r.w += F[u] * t1.y;
            }
        }
        return r;
    };

    float4 h0 = make_float4(0.f, 0.f, 0.f, 0.f);
    float4 h1 = hrow(0), h2 = hrow(1);
    for (int y = 0; y < 64; ++y) {
        float4 h3 = hrow(y + 2);
        float4 o;
        o.x = 0.25f * h0.x + 0.75f * h1.x + 0.75f * h2.x + 0.25f * h3.x;
        o.y = 0.25f * h0.y + 0.75f * h1.y + 0.75f * h2.y + 0.25f * h3.y;
        o.z = 0.25f * h0.z + 0.75f * h1.z + 0.75f * h2.z + 0.25f * h3.z;
        o.w = 0.25f * h0.w + 0.75f * h1.w + 0.75f * h2.w + 0.25f * h3.w;
        float nz = noise[((size_t)b * 64 + y) * 64 + xi];
        float4 v;
        v.x = o.x * dvv.x + snv.x * nz + biv.x;
        v.y = o.y * dvv.y + snv.y * nz + biv.y;
        v.z = o.z * dvv.z + snv.z * nz + biv.z;
        v.w = o.w * dvv.w + snv.w * nz + biv.w;
        v.x = v.x >= 0.f ? v.x : 0.2f * v.x;
        v.y = v.y >= 0.f ? v.y : 0.2f * v.y;
        v.z = v.z >= 0.f ? v.z : 0.2f * v.z;
        v.w = v.w >= 0.f ? v.w : 0.2f * v.w;
        size_t off = (((size_t)b * 64 + y) * 64 + xi) * 512 + c;
        __half2 p0 = __floats2half2_rn(v.x * s2v.x * WS9F, v.y * s2v.y * WS9F);
        __half2 p1 = __floats2half2_rn(v.z * s2v.z * WS9F, v.w * s2v.w * WS9F);
        ((__half2*)(xout + off))[0] = p0;
        ((__half2*)(xout + off))[1] = p1;
        h0 = h1; h1 = h2; h2 = h3;
    }
}

// ---- toRGB ----
__global__ void torgb_kernel(const float* __restrict__ x2, float* __restrict__ rgb,
                             const float* __restrict__ biasr) {
    const int warp = threadIdx.x >> 5, lane = threadIdx.x & 31;
    const int pix = blockIdx.x * 8 + warp;
    const int b = pix >> 12;
    const float* xp = x2 + (size_t)pix * 512;
    const float* sp = g_sr + b * 512;
    float r0 = 0.f, r1 = 0.f, r2 = 0.f;
#pragma unroll
    for (int k = 0; k < 4; ++k) {
        int c = lane * 4 + k * 128;
        float4 xv = *(const float4*)(xp + c);
        float4 sv = *(const float4*)(sp + c);
        xv.x *= sv.x; xv.y *= sv.y; xv.z *= sv.z; xv.w *= sv.w;
        float4 w0 = *(const float4*)(g_wr3 + 0 * 512 + c);
        float4 w1 = *(const float4*)(g_wr3 + 1 * 512 + c);
        float4 w2 = *(const float4*)(g_wr3 + 2 * 512 + c);
        r0 += xv.x * w0.x + xv.y * w0.y + xv.z * w0.z + xv.w * w0.w;
        r1 += xv.x * w1.x + xv.y * w1.y + xv.z * w1.z + xv.w * w1.w;
        r2 += xv.x * w2.x + xv.y * w2.y + xv.z * w2.z + xv.w * w2.w;
    }
#pragma unroll
    for (int off = 16; off > 0; off >>= 1) {
        r0 += __shfl_xor_sync(0xffffffffu, r0, off);
        r1 += __shfl_xor_sync(0xffffffffu, r1, off);
        r2 += __shfl_xor_sync(0xffffffffu, r2, off);
    }
    if (lane == 0) {
        float v0 = r0 + biasr[0], v1 = r1 + biasr[1], v2 = r2 + biasr[2];
        rgb[(size_t)pix * 3 + 0] = v0 >= 0.f ? v0 : 0.2f * v0;
        rgb[(size_t)pix * 3 + 1] = v1 >= 0.f ? v1 : 0.2f * v1;
        rgb[(size_t)pix * 3 + 2] = v2 >= 0.f ? v2 : 0.2f * v2;
    }
}

// ---- launch ----
extern "C" void kernel_launch(void* const* d_in, const int* in_sizes, int n_in,
                              void* d_out, int out_size) {
    const float* x       = (const float*)d_in[0];
    const float* w       = (const float*)d_in[1];
    const float* noise1  = (const float*)d_in[2];
    const float* noise2  = (const float*)d_in[3];
    const float* fcl1_w  = (const float*)d_in[4];
    const float* fcl1_b  = (const float*)d_in[5];
    const float* conv1_w = (const float*)d_in[6];
    const float* sn1     = (const float*)d_in[7];
    const float* bias1   = (const float*)d_in[8];
    const float* fcl2_w  = (const float*)d_in[9];
    const float* fcl2_b  = (const float*)d_in[10];
    const float* conv2_w = (const float*)d_in[11];
    const float* sn2     = (const float*)d_in[12];
    const float* bias2   = (const float*)d_in[13];
    const float* fclr_w  = (const float*)d_in[14];
    const float* fclr_b  = (const float*)d_in[15];
    const float* convr_w = (const float*)d_in[16];
    const float* biasr   = (const float*)d_in[17];

    float* x2out  = (float*)d_out;
    float* rgbout = x2out + (size_t)B_ * 64 * 64 * 512;

    float *s1, *s2, *sr, *dd;
    __half *ydc, *a1, *a2, *wh;
    cudaGetSymbolAddress((void**)&s1, g_s1);
    cudaGetSymbolAddress((void**)&s2, g_s2);
    cudaGetSymbolAddress((void**)&sr, g_sr);
    cudaGetSymbolAddress((void**)&dd, g_d);
    cudaGetSymbolAddress((void**)&ydc, g_ydc);
    cudaGetSymbolAddress((void**)&a1, g_a1);
    cudaGetSymbolAddress((void**)&a2, g_a2);
    cudaGetSymbolAddress((void**)&wh, g_wh);
    float* d2 = dd + B_ * 512;

    cudaFuncSetAttribute(mma_conv_kernel, cudaFuncAttributeMaxDynamicSharedMemorySize, SMEMSZ);

    fcl3_kernel<<<dim3(B_, 3), 512>>>(w, fcl1_w, fcl1_b, s1, fcl2_w, fcl2_b, s2,
                                      fclr_w, fclr_b, sr);
    a_kernel<<<dim3(512, 2), 512>>>(conv1_w, conv2_w);
    d_kernel<<<dim3(B_, 2), 512>>>();
    wr3_kernel<<<1, 512>>>(convr_w);
    prep_a1<<<8192, 256>>>(x);
    wprep_kernel<<<dim3(16, 16, 18), 256>>>(conv1_w, conv2_w);

    // deconv: 4 parity classes in ONE launch (grid.z = class), M=128 input-px tiles
    mma_conv_kernel<<<dim3(4, B_ * 8, 4), 256, SMEMSZ>>>(
        a1, 32, 32, wh, /*tapsBase=*/0, /*tilesPerImg=*/8, /*pxs=*/5, /*pxm=*/31,
        nullptr, ydc, nullptr, nullptr, nullptr, nullptr);

    blur_kernel<<<B_ * 32, 256>>>(ydc, a2, noise1, sn1, bias1);

    // conv2: 3x3 SAME, fused demod/noise/bias/lrelu -> d_out, M=128 px tiles
    mma_conv_kernel<<<dim3(4, B_ * 32, 1), 256, SMEMSZ>>>(
        a2, 64, 64, wh + (size_t)9 * 512 * 512, /*tapsBase=*/4, /*tilesPerImg=*/32,
        /*pxs=*/6, /*pxm=*/63,
        x2out, nullptr, d2, noise2, sn2, bias2);

    torgb_kernel<<<(B_ * 64 * 64) / 8, 256>>>(x2out, rgbout, biasr);
}

// round 12
// speedup vs baseline: 1.2175x; 1.0700x over previous
#include <cuda_runtime.h>
#include <cuda_fp16.h>
#include <math.h>
#include <stdint.h>

#define B_   16

// ---- base-PTX helpers ----
__device__ __forceinline__ uint32_t smem_u32(const void* p) {
    uint32_t a;
    asm("{ .reg .u64 t; cvta.to.shared.u64 t, %1; cvt.u32.u64 %0, t; }" : "=r"(a) : "l"(p));
    return a;
}
#define LDSM4(r0, r1, r2, r3, addr) \
    asm volatile("ldmatrix.sync.aligned.m8n8.x4.shared.b16 {%0,%1,%2,%3}, [%4];" \
        : "=r"(r0), "=r"(r1), "=r"(r2), "=r"(r3) : "r"(addr))
__device__ __forceinline__ void mma16816(float* c, const uint32_t* a, const uint32_t* b) {
    asm volatile("mma.sync.aligned.m16n8k16.row.col.f32.f16.f16.f32 "
                 "{%0,%1,%2,%3}, {%4,%5,%6,%7}, {%8,%9}, {%0,%1,%2,%3};"
                 : "+f"(c[0]), "+f"(c[1]), "+f"(c[2]), "+f"(c[3])
                 : "r"(a[0]), "r"(a[1]), "r"(a[2]), "r"(a[3]), "r"(b[0]), "r"(b[1]));
}
__device__ __forceinline__ void cpa16(uint32_t dst, const void* src, uint32_t sz) {
    asm volatile("cp.async.cg.shared.global [%0], [%1], 16, %2;" :: "r"(dst), "l"(src), "r"(sz));
}
#define CP_COMMIT() asm volatile("cp.async.commit_group;")
#define CP_WAIT0()  asm volatile("cp.async.wait_group 0;")
#define CP_WAIT1()  asm volatile("cp.async.wait_group 1;")

// ---- scratch ----
__device__ float g_s1[B_ * 512];
__device__ float g_s2[B_ * 512];
__device__ float g_sr[B_ * 512];
__device__ float g_d[2][B_ * 512];
__device__ float g_A[2][512 * 512];
__device__ float g_wr3[3 * 512];
__device__ __half g_ydc[(size_t)B_ * 64 * 64 * 512];  // deconv out (pre-blur), fp16
__device__ __half g_a1[(size_t)B_ * 32 * 32 * 512];   // x*s1*wscale, fp16
__device__ __half g_a2[(size_t)B_ * 64 * 64 * 512];   // block1 out *s2*wscale, fp16
__device__ __half g_wh[(size_t)2 * 9 * 512 * 512];    // wT[conv][t][cout][cin] fp16

static __constant__ float kFclScale = 0.04419417382415922f;   // 1/sqrt(512)
#define WS9F 0.014731391274719738f                            // 1/sqrt(4608)

// taps: classes 0..3 = deconv parity (rh*2+rw), class 4 = conv2 3x3
struct TapList { int n; int dy[9]; int dx[9]; int wi[9]; };
__constant__ TapList c_taps[5] = {
    {4, {-1,-1, 0, 0, 0,0,0,0,0}, {-1, 0,-1, 0, 0,0,0,0,0}, {0,2,6,8, 0,0,0,0,0}},
    {2, {-1, 0, 0, 0, 0,0,0,0,0}, { 0, 0, 0, 0, 0,0,0,0,0}, {1,7, 0,0,0,0,0,0,0}},
    {2, { 0, 0, 0, 0, 0,0,0,0,0}, {-1, 0, 0, 0, 0,0,0,0,0}, {3,5, 0,0,0,0,0,0,0}},
    {1, { 0, 0, 0, 0, 0,0,0,0,0}, { 0, 0, 0, 0, 0,0,0,0,0}, {4, 0,0,0,0,0,0,0,0}},
    {9, {-1,-1,-1, 0, 0, 0, 1, 1, 1}, {-1, 0, 1,-1, 0, 1,-1, 0, 1}, {0,1,2,3,4,5,6,7,8}}
};
// {ymul, yadd, xmul, xadd}
__constant__ int4 c_geo[5] = { {2,0,2,0}, {2,0,2,1}, {2,1,2,0}, {2,1,2,1}, {1,0,1,0} };

// ---- small kernels ----
__global__ void fcl3_kernel(const float* __restrict__ w,
                            const float* __restrict__ fw1, const float* __restrict__ fb1, float* __restrict__ o1,
                            const float* __restrict__ fw2, const float* __restrict__ fb2, float* __restrict__ o2,
                            const float* __restrict__ fw3, const float* __restrict__ fb3, float* __restrict__ o3) {
    __shared__ float wsh[512];
    int b = blockIdx.x, c = threadIdx.x, sel = blockIdx.y;
    const float* fw = sel == 0 ? fw1 : (sel == 1 ? fw2 : fw3);
    const float* fb = sel == 0 ? fb1 : (sel == 1 ? fb2 : fb3);
    float* o = sel == 0 ? o1 : (sel == 1 ? o2 : o3);
    wsh[c] = w[b * 512 + c];
    __syncthreads();
    float acc = 0.f;
#pragma unroll 8
    for (int k = 0; k < 512; ++k) acc += wsh[k] * fw[k * 512 + c];
    o[b * 512 + c] = acc * kFclScale + fb[c];
}

__global__ void a_kernel(const float* __restrict__ w1, const float* __restrict__ w2) {
    int cin = blockIdx.x, sel = blockIdx.y, c = threadIdx.x;
    const float* w = sel ? w2 : w1;
    float acc = 0.f;
#pragma unroll
    for (int t = 0; t < 9; ++t) {
        float v = w[((size_t)t * 512 + cin) * 512 + c];
        acc += v * v;
    }
    g_A[sel][cin * 512 + c] = acc * (1.0f / 4608.0f);
}

__global__ void d_kernel() {
    __shared__ float ssq[512];
    int b = blockIdx.x, sel = blockIdx.y, c = threadIdx.x;
    const float* s = sel ? g_s2 : g_s1;
    float sv = s[b * 512 + c];
    ssq[c] = sv * sv;
    __syncthreads();
    float acc = 0.f;
#pragma unroll 8
    for (int k = 0; k < 512; ++k) acc += g_A[sel][k * 512 + c] * ssq[k];
    g_d[sel][b * 512 + c] = rsqrtf(acc + 1e-8f);
}

__global__ void wr3_kernel(const float* __restrict__ wr) {
    int c = threadIdx.x;
#pragma unroll
    for (int j = 0; j < 3; ++j) g_wr3[j * 512 + c] = wr[c * 3 + j] * kFclScale;
}

// A1 = fp16(x * s1 * wscale)
__global__ void prep_a1(const float* __restrict__ x) {
    int idx = blockIdx.x * 256 + threadIdx.x;  // float4 units
    float4 v = ((const float4*)x)[idx];
    int b = idx >> 17, c4 = idx & 127;
    float4 s = ((const float4*)g_s1)[b * 128 + c4];
    __half2 h0 = __floats2half2_rn(v.x * s.x * WS9F, v.y * s.y * WS9F);
    __half2 h1 = __floats2half2_rn(v.z * s.z * WS9F, v.w * s.w * WS9F);
    ((__half2*)g_a1)[idx * 2] = h0;
    ((__half2*)g_a1)[idx * 2 + 1] = h1;
}

// wT[conv][t][cout][cin] = fp16(transpose(conv_w[t])), one conv per launch
__global__ void wprep_kernel(const float* __restrict__ w, int conv) {
    __shared__ float tile[32][33];
    int t = blockIdx.z;
    __half* dh = g_wh + (size_t)conv * 9 * 512 * 512;
    int ci0 = blockIdx.x * 32, co0 = blockIdx.y * 32;
    int tx = threadIdx.x & 31, ty = threadIdx.x >> 5;
#pragma unroll
    for (int r = 0; r < 4; ++r)
        tile[ty + r * 8][tx] = w[(((size_t)t * 512 + ci0 + ty + r * 8) << 9) + co0 + tx];
    __syncthreads();
#pragma unroll
    for (int r = 0; r < 4; ++r) {
        int co = co0 + ty + r * 8;
        dh[(((size_t)t * 512 + co) << 9) + ci0 + tx] = __float2half_rn(tile[tx][ty + r * 8]);
    }
}

// ---- HMMA implicit-GEMM conv: CTA 128px x 128cout, 8 warps (4M x 2N), K-stage 64 ----
#define ASTAGE 18432         // 128 rows * 144B
#define STAGE  36864         // A + B(128 rows * 144B)
#define SMEMSZ (3 * STAGE)   // 110592 -> 2 CTAs/SM

__global__ __launch_bounds__(256, 2)
void mma_conv_kernel(const __half* __restrict__ xin, int Hin, int Win,
                     const __half* __restrict__ wh,
                     int tapsBase, int tilesPerImg, int pxs, int pxm,
                     float* __restrict__ outf, __half* __restrict__ outh,
                     const float* __restrict__ dvec, const float* __restrict__ noise,
                     const float* __restrict__ snoise, const float* __restrict__ bias) {
    extern __shared__ __align__(16) char smem[];
    const uint32_t su = smem_u32(smem);
    const int tid = threadIdx.x, lane = tid & 31, wid = tid >> 5;
    const int sel = tapsBase + blockIdx.z;
    const int b = blockIdx.y / tilesPerImg;
    const int a0 = (blockIdx.y % tilesPerImg) * (128 >> pxs);
    const int cout0 = blockIdx.x * 128;
    const int m0 = (wid & 3) * 32, n0 = (wid >> 2) * 64;

    float acc[2][8][4];
#pragma unroll
    for (int i = 0; i < 2; ++i)
#pragma unroll
        for (int j = 0; j < 8; ++j)
#pragma unroll
            for (int k = 0; k < 4; ++k) acc[i][j][k] = 0.f;

    const int S = c_taps[sel].n * 8;

    auto load_stage = [&](int st, int p) {
        int t = st >> 3, ck = (st & 7) << 6;
        uint32_t base = su + p * STAGE;
        int dy = c_taps[sel].dy[t], dx = c_taps[sel].dx[t];
#pragma unroll
        for (int i = 0; i < 4; ++i) {   // A: 128 rows x 64 fp16
            int id = tid + i * 256;
            int r = id >> 3, seg = id & 7;
            int iy = a0 + (r >> pxs) + dy, ix = (r & pxm) + dx;
            bool ok = ((unsigned)iy < (unsigned)Hin) && ((unsigned)ix < (unsigned)Win);
            const void* src = xin + ((((size_t)b * Hin + (ok ? iy : 0)) * Win + (ok ? ix : 0)) << 9)
                              + ck + (seg << 3);
            cpa16(base + r * 144 + seg * 16, src, ok ? 16u : 0u);
        }
        const __half* wt = wh + (((size_t)(c_taps[sel].wi[t] * 512 + cout0)) << 9) + ck;
#pragma unroll
        for (int i = 0; i < 4; ++i) {   // B: 128 rows x 64 fp16
            int id = tid + i * 256;
            int row = id >> 3, seg = id & 7;
            cpa16(base + ASTAGE + row * 144 + seg * 16, wt + ((size_t)row << 9) + (seg << 3), 16u);
        }
    };

    auto compute = [&](int p) {
        uint32_t Ab = su + p * STAGE;
        uint32_t Bb = Ab + ASTAGE;
#pragma unroll
        for (int kk = 0; kk < 64; kk += 16) {
            uint32_t a[2][4];
#pragma unroll
            for (int mi = 0; mi < 2; ++mi) {
                uint32_t addr = Ab + (m0 + mi * 16 + (lane & 15)) * 144
                                + (kk + ((lane >> 4) << 3)) * 2;
                LDSM4(a[mi][0], a[mi][1], a[mi][2], a[mi][3], addr);
            }
            uint32_t bb[8][2];
#pragma unroll
            for (int ng = 0; ng < 4; ++ng) {
                int row = n0 + ng * 16 + (lane & 7) + ((lane >> 4) << 3);
                uint32_t addr = Bb + row * 144 + (kk + (((lane >> 3) & 1) << 3)) * 2;
                uint32_t r0, r1, r2, r3;
                LDSM4(r0, r1, r2, r3, addr);
                bb[ng * 2][0] = r0;     bb[ng * 2][1] = r1;
                bb[ng * 2 + 1][0] = r2; bb[ng * 2 + 1][1] = r3;
            }
#pragma unroll
            for (int mi = 0; mi < 2; ++mi)
#pragma unroll
                for (int ni = 0; ni < 8; ++ni)
                    mma16816(acc[mi][ni], a[mi], bb[ni]);
        }
    };

    // single-sync pipeline: wait(st) -> sync -> compute(st) -> load(st+2)
    load_stage(0, 0); CP_COMMIT();
    if (S > 1) { load_stage(1, 1); CP_COMMIT(); }
    for (int st = 0; st < S; ++st) {
        if (st + 1 < S) { CP_WAIT1(); } else { CP_WAIT0(); }
        __syncthreads();
        compute(st % 3);
        if (st + 2 < S) { load_stage(st + 2, (st + 2) % 3); CP_COMMIT(); }
    }

    // epilogue
    const int4 geo = c_geo[sel];
    const int quad = lane >> 2, tq = lane & 3;
    if (dvec) {
        float2 dv2[8], sn2[8], bi2[8];
#pragma unroll
        for (int ni = 0; ni < 8; ++ni) {
            int col = cout0 + n0 + ni * 8 + tq * 2;
            dv2[ni] = *(const float2*)(dvec + b * 512 + col);
            sn2[ni] = *(const float2*)(snoise + col);
            bi2[ni] = *(const float2*)(bias + col);
        }
#pragma unroll
        for (int mi = 0; mi < 2; ++mi)
#pragma unroll
            for (int h = 0; h < 2; ++h) {
                int r = m0 + mi * 16 + quad + h * 8;
                int oy = (a0 + (r >> pxs)) * geo.x + geo.y;
                int ox = (r & pxm) * geo.z + geo.w;
                size_t pbase = (((size_t)b * 64 + oy) * 64 + ox) << 9;
                float nz = noise[(((size_t)b * 64 + oy) << 6) + ox];
#pragma unroll
                for (int ni = 0; ni < 8; ++ni) {
                    float c0 = acc[mi][ni][h * 2], c1 = acc[mi][ni][h * 2 + 1];
                    float2 v;
                    v.x = c0 * dv2[ni].x + sn2[ni].x * nz + bi2[ni].x;
                    v.y = c1 * dv2[ni].y + sn2[ni].y * nz + bi2[ni].y;
                    v.x = v.x >= 0.f ? v.x : 0.2f * v.x;
                    v.y = v.y >= 0.f ? v.y : 0.2f * v.y;
                    *(float2*)(outf + pbase + cout0 + n0 + ni * 8 + tq * 2) = v;
                }
            }
    } else {
#pragma unroll
        for (int mi = 0; mi < 2; ++mi)
#pragma unroll
            for (int h = 0; h < 2; ++h) {
                int r = m0 + mi * 16 + quad + h * 8;
                int oy = (a0 + (r >> pxs)) * geo.x + geo.y;
                int ox = (r & pxm) * geo.z + geo.w;
                size_t pbase = (((size_t)b * 64 + oy) * 64 + ox) << 9;
#pragma unroll
                for (int ni = 0; ni < 8; ++ni) {
                    __half2 v = __floats2half2_rn(acc[mi][ni][h * 2], acc[mi][ni][h * 2 + 1]);
                    *(__half2*)(outh + pbase + cout0 + n0 + ni * 8 + tq * 2) = v;
                }
            }
    }
}

// ---- blur (fp16 in) + demod1 + noise + bias + lrelu -> fp16 (v*s2*wscale) ----
__global__ void blur_kernel(const __half* __restrict__ ydc, __half* __restrict__ xout,
                            const float* __restrict__ noise, const float* __restrict__ snoise,
                            const float* __restrict__ bias) {
    const int cg = threadIdx.x & 127, c = cg * 4;
    const int xi = (blockIdx.x % 32) * 2 + (threadIdx.x >> 7);
    const int b = blockIdx.x / 32;
    const float F[4] = {0.25f, 0.75f, 0.75f, 0.25f};

    float4 dvv = *(const float4*)(&g_d[0][b * 512 + c]);
    float4 snv = *(const float4*)(snoise + c);
    float4 biv = *(const float4*)(bias + c);
    float4 s2v = *(const float4*)(&g_s2[b * 512 + c]);

    auto hrow = [&](int v) -> float4 {
        float4 r = make_float4(0.f, 0.f, 0.f, 0.f);
        if (v < 0 || v >= 64) return r;
        const __half* base = ydc + (((size_t)b * 64 + v) * 64) * 512 + c;
#pragma unroll
        for (int u = 0; u < 4; ++u) {
            int xx = xi + u - 1;
            if (xx >= 0 && xx < 64) {
                const __half2* p = (const __half2*)(base + (size_t)xx * 512);
                float2 t0 = __half22float2(p[0]);
                float2 t1 = __half22float2(p[1]);
                r.x += F[u] * t0.x; r.y += F[u] * t0.y; r.z += F[u] * t1.x; r.w += F[u] * t1.y;
            }
        }
        return r;
    };

    float4 h0 = make_float4(0.f, 0.f, 0.f, 0.f);
    float4 h1 = hrow(0), h2 = hrow(1);
    for (int y = 0; y < 64; ++y) {
        float4 h3 = hrow(y + 2);
        float4 o;
        o.x = 0.25f * h0.x + 0.75f * h1.x + 0.75f * h2.x + 0.25f * h3.x;
        o.y = 0.25f * h0.y + 0.75f * h1.y + 0.75f * h2.y + 0.25f * h3.y;
        o.z = 0.25f * h0.z + 0.75f * h1.z + 0.75f * h2.z + 0.25f * h3.z;
        o.w = 0.25f * h0.w + 0.75f * h1.w + 0.75f * h2.w + 0.25f * h3.w;
        float nz = noise[((size_t)b * 64 + y) * 64 + xi];
        float4 v;
        v.x = o.x * dvv.x + snv.x * nz + biv.x;
        v.y = o.y * dvv.y + snv.y * nz + biv.y;
        v.z = o.z * dvv.z + snv.z * nz + biv.z;
        v.w = o.w * dvv.w + snv.w * nz + biv.w;
        v.x = v.x >= 0.f ? v.x : 0.2f * v.x;
        v.y = v.y >= 0.f ? v.y : 0.2f * v.y;
        v.z = v.z >= 0.f ? v.z : 0.2f * v.z;
        v.w = v.w >= 0.f ? v.w : 0.2f * v.w;
        size_t off = (((size_t)b * 64 + y) * 64 + xi) * 512 + c;
        __half2 p0 = __floats2half2_rn(v.x * s2v.x * WS9F, v.y * s2v.y * WS9F);
        __half2 p1 = __floats2half2_rn(v.z * s2v.z * WS9F, v.w * s2v.w * WS9F);
        ((__half2*)(xout + off))[0] = p0;
        ((__half2*)(xout + off))[1] = p1;
        h0 = h1; h1 = h2; h2 = h3;
    }
}

// ---- toRGB ----
__global__ void torgb_kernel(const float* __restrict__ x2, float* __restrict__ rgb,
                             const float* __restrict__ biasr) {
    const int warp = threadIdx.x >> 5, lane = threadIdx.x & 31;
    const int pix = blockIdx.x * 8 + warp;
    const int b = pix >> 12;
    const float* xp = x2 + (size_t)pix * 512;
    const float* sp = g_sr + b * 512;
    float r0 = 0.f, r1 = 0.f, r2 = 0.f;
#pragma unroll
    for (int k = 0; k < 4; ++k) {
        int c = lane * 4 + k * 128;
        float4 xv = *(const float4*)(xp + c);
        float4 sv = *(const float4*)(sp + c);
        xv.x *= sv.x; xv.y *= sv.y; xv.z *= sv.z; xv.w *= sv.w;
        float4 w0 = *(const float4*)(g_wr3 + 0 * 512 + c);
        float4 w1 = *(const float4*)(g_wr3 + 1 * 512 + c);
        float4 w2 = *(const float4*)(g_wr3 + 2 * 512 + c);
        r0 += xv.x * w0.x + xv.y * w0.y + xv.z * w0.z + xv.w * w0.w;
        r1 += xv.x * w1.x + xv.y * w1.y + xv.z * w1.z + xv.w * w1.w;
        r2 += xv.x * w2.x + xv.y * w2.y + xv.z * w2.z + xv.w * w2.w;
    }
#pragma unroll
    for (int off = 16; off > 0; off >>= 1) {
        r0 += __shfl_xor_sync(0xffffffffu, r0, off);
        r1 += __shfl_xor_sync(0xffffffffu, r1, off);
        r2 += __shfl_xor_sync(0xffffffffu, r2, off);
    }
    if (lane == 0) {
        float v0 = r0 + biasr[0], v1 = r1 + biasr[1], v2 = r2 + biasr[2];
        rgb[(size_t)pix * 3 + 0] = v0 >= 0.f ? v0 : 0.2f * v0;
        rgb[(size_t)pix * 3 + 1] = v1 >= 0.f ? v1 : 0.2f * v1;
        rgb[(size_t)pix * 3 + 2] = v2 >= 0.f ? v2 : 0.2f * v2;
    }
}

// ---- launch ----
extern "C" void kernel_launch(void* const* d_in, const int* in_sizes, int n_in,
                              void* d_out, int out_size) {
    const float* x       = (const float*)d_in[0];
    const float* w       = (const float*)d_in[1];
    const float* noise1  = (const float*)d_in[2];
    const float* noise2  = (const float*)d_in[3];
    const float* fcl1_w  = (const float*)d_in[4];
    const float* fcl1_b  = (const float*)d_in[5];
    const float* conv1_w = (const float*)d_in[6];
    const float* sn1     = (const float*)d_in[7];
    const float* bias1   = (const float*)d_in[8];
    const float* fcl2_w  = (const float*)d_in[9];
    const float* fcl2_b  = (const float*)d_in[10];
    const float* conv2_w = (const float*)d_in[11];
    const float* sn2     = (const float*)d_in[12];
    const float* bias2   = (const float*)d_in[13];
    const float* fclr_w  = (const float*)d_in[14];
    const float* fclr_b  = (const float*)d_in[15];
    const float* convr_w = (const float*)d_in[16];
    const float* biasr   = (const float*)d_in[17];

    float* x2out  = (float*)d_out;
    float* rgbout = x2out + (size_t)B_ * 64 * 64 * 512;

    float *s1, *s2, *sr, *dd;
    __half *ydc, *a1, *a2, *wh;
    cudaGetSymbolAddress((void**)&s1, g_s1);
    cudaGetSymbolAddress((void**)&s2, g_s2);
    cudaGetSymbolAddress((void**)&sr, g_sr);
    cudaGetSymbolAddress((void**)&dd, g_d);
    cudaGetSymbolAddress((void**)&ydc, g_ydc);
    cudaGetSymbolAddress((void**)&a1, g_a1);
    cudaGetSymbolAddress((void**)&a2, g_a2);
    cudaGetSymbolAddress((void**)&wh, g_wh);
    float* d2 = dd + B_ * 512;

    // one-time resources (created on the first, non-captured correctness call)
    static cudaStream_t s_aux = nullptr;
    static cudaEvent_t ev_fork = nullptr, ev_join = nullptr;
    static bool attrSet = false;
    if (!s_aux) {
        cudaStreamCreateWithFlags(&s_aux, cudaStreamNonBlocking);
        cudaEventCreateWithFlags(&ev_fork, cudaEventDisableTiming);
        cudaEventCreateWithFlags(&ev_join, cudaEventDisableTiming);
    }
    if (!attrSet) {
        cudaFuncSetAttribute(mma_conv_kernel, cudaFuncAttributeMaxDynamicSharedMemorySize, SMEMSZ);
        attrSet = true;
    }

    // styles first (needed by both branches)
    fcl3_kernel<<<dim3(B_, 3), 512>>>(w, fcl1_w, fcl1_b, s1, fcl2_w, fcl2_b, s2,
                                      fclr_w, fclr_b, sr);

    // fork: conv2-only prep on aux stream, overlapped with deconv path
    cudaEventRecord(ev_fork, 0);
    cudaStreamWaitEvent(s_aux, ev_fork, 0);
    a_kernel<<<dim3(512, 2), 512, 0, s_aux>>>(conv1_w, conv2_w);
    d_kernel<<<dim3(B_, 2), 512, 0, s_aux>>>();
    wr3_kernel<<<1, 512, 0, s_aux>>>(convr_w);
    wprep_kernel<<<dim3(16, 16, 9), 256, 0, s_aux>>>(conv2_w, 1);
    cudaEventRecord(ev_join, s_aux);

    // main chain: conv1 prep -> deconv -> blur
    prep_a1<<<8192, 256>>>(x);
    wprep_kernel<<<dim3(16, 16, 9), 256>>>(conv1_w, 0);

    // deconv: 4 parity classes in ONE launch (grid.z = class), M=128 input-px tiles
    mma_conv_kernel<<<dim3(4, B_ * 8, 4), 256, SMEMSZ>>>(
        a1, 32, 32, wh, /*tapsBase=*/0, /*tilesPerImg=*/8, /*pxs=*/5, /*pxm=*/31,
        nullptr, ydc, nullptr, nullptr, nullptr, nullptr);

    blur_kernel<<<B_ * 32, 256>>>(ydc, a2, noise1, sn1, bias1);

    // join aux prep before conv2
    cudaStreamWaitEvent(0, ev_join, 0);

    // conv2: 3x3 SAME, fused demod/noise/bias/lrelu -> d_out, M=128 px tiles
    mma_conv_kernel<<<dim3(4, B_ * 32, 1), 256, SMEMSZ>>>(
        a2, 64, 64, wh + (size_t)9 * 512 * 512, /*tapsBase=*/4, /*tilesPerImg=*/32,
        /*pxs=*/6, /*pxm=*/63,
        x2out, nullptr, d2, noise2, sn2, bias2);

    torgb_kernel<<<(B_ * 64 * 64) / 8, 256>>>(x2out, rgbout, biasr);
}

// round 14
// speedup vs baseline: 1.2523x; 1.0286x over previous
#include <cuda_runtime.h>
#include <cuda_fp16.h>
#include <math.h>
#include <stdint.h>

#define B_   16

// ---- base-PTX helpers ----
__device__ __forceinline__ uint32_t smem_u32(const void* p) {
    uint32_t a;
    asm("{ .reg .u64 t; cvta.to.shared.u64 t, %1; cvt.u32.u64 %0, t; }" : "=r"(a) : "l"(p));
    return a;
}
#define LDSM4(r0, r1, r2, r3, addr) \
    asm volatile("ldmatrix.sync.aligned.m8n8.x4.shared.b16 {%0,%1,%2,%3}, [%4];" \
        : "=r"(r0), "=r"(r1), "=r"(r2), "=r"(r3) : "r"(addr))
__device__ __forceinline__ void mma16816(float* c, const uint32_t* a, const uint32_t* b) {
    asm volatile("mma.sync.aligned.m16n8k16.row.col.f32.f16.f16.f32 "
                 "{%0,%1,%2,%3}, {%4,%5,%6,%7}, {%8,%9}, {%0,%1,%2,%3};"
                 : "+f"(c[0]), "+f"(c[1]), "+f"(c[2]), "+f"(c[3])
                 : "r"(a[0]), "r"(a[1]), "r"(a[2]), "r"(a[3]), "r"(b[0]), "r"(b[1]));
}
__device__ __forceinline__ void cpa16(uint32_t dst, const void* src, uint32_t sz) {
    asm volatile("cp.async.cg.shared.global [%0], [%1], 16, %2;" :: "r"(dst), "l"(src), "r"(sz));
}
#define CP_COMMIT() asm volatile("cp.async.commit_group;")
#define CP_WAIT0()  asm volatile("cp.async.wait_group 0;")
#define CP_WAIT1()  asm volatile("cp.async.wait_group 1;")

// ---- scratch ----
__device__ float g_s1[B_ * 512];
__device__ float g_s2[B_ * 512];
__device__ float g_sr[B_ * 512];
__device__ float g_d[2][B_ * 512];
__device__ float g_A[2][512 * 512];
__device__ float g_srw[B_ * 3 * 512];                 // sr * convr_w * fclscale
__device__ __half g_ydc[(size_t)B_ * 64 * 64 * 512];  // deconv out (pre-blur), fp16
__device__ __half g_a1[(size_t)B_ * 32 * 32 * 512];   // x*s1*wscale, fp16
__device__ __half g_a2[(size_t)B_ * 64 * 64 * 512];   // block1 out *s2*wscale, fp16
__device__ __half g_wh[(size_t)2 * 9 * 512 * 512];    // wT[conv][t][cout][cin] fp16

static __constant__ float kFclScale = 0.04419417382415922f;   // 1/sqrt(512)
#define WS9F 0.014731391274719738f                            // 1/sqrt(4608)

// taps: classes 0..3 = deconv parity (rh*2+rw), class 4 = conv2 3x3
struct TapList { int n; int dy[9]; int dx[9]; int wi[9]; };
__constant__ TapList c_taps[5] = {
    {4, {-1,-1, 0, 0, 0,0,0,0,0}, {-1, 0,-1, 0, 0,0,0,0,0}, {0,2,6,8, 0,0,0,0,0}},
    {2, {-1, 0, 0, 0, 0,0,0,0,0}, { 0, 0, 0, 0, 0,0,0,0,0}, {1,7, 0,0,0,0,0,0,0}},
    {2, { 0, 0, 0, 0, 0,0,0,0,0}, {-1, 0, 0, 0, 0,0,0,0,0}, {3,5, 0,0,0,0,0,0,0}},
    {1, { 0, 0, 0, 0, 0,0,0,0,0}, { 0, 0, 0, 0, 0,0,0,0,0}, {4, 0,0,0,0,0,0,0,0}},
    {9, {-1,-1,-1, 0, 0, 0, 1, 1, 1}, {-1, 0, 1,-1, 0, 1,-1, 0, 1}, {0,1,2,3,4,5,6,7,8}}
};
// {ymul, yadd, xmul, xadd}
__constant__ int4 c_geo[5] = { {2,0,2,0}, {2,0,2,1}, {2,1,2,0}, {2,1,2,1}, {1,0,1,0} };

// ---- small kernels ----
__global__ void fcl3_kernel(const float* __restrict__ w,
                            const float* __restrict__ fw1, const float* __restrict__ fb1, float* __restrict__ o1,
                            const float* __restrict__ fw2, const float* __restrict__ fb2, float* __restrict__ o2,
                            const float* __restrict__ fw3, const float* __restrict__ fb3, float* __restrict__ o3) {
    __shared__ float wsh[512];
    int b = blockIdx.x, c = threadIdx.x, sel = blockIdx.y;
    const float* fw = sel == 0 ? fw1 : (sel == 1 ? fw2 : fw3);
    const float* fb = sel == 0 ? fb1 : (sel == 1 ? fb2 : fb3);
    float* o = sel == 0 ? o1 : (sel == 1 ? o2 : o3);
    wsh[c] = w[b * 512 + c];
    __syncthreads();
    float acc = 0.f;
#pragma unroll 8
    for (int k = 0; k < 512; ++k) acc += wsh[k] * fw[k * 512 + c];
    o[b * 512 + c] = acc * kFclScale + fb[c];
}

__global__ void a_kernel(const float* __restrict__ w1, const float* __restrict__ w2) {
    int cin = blockIdx.x, sel = blockIdx.y, c = threadIdx.x;
    const float* w = sel ? w2 : w1;
    float acc = 0.f;
#pragma unroll
    for (int t = 0; t < 9; ++t) {
        float v = w[((size_t)t * 512 + cin) * 512 + c];
        acc += v * v;
    }
    g_A[sel][cin * 512 + c] = acc * (1.0f / 4608.0f);
}

__global__ void d_kernel() {
    __shared__ float ssq[512];
    int b = blockIdx.x, sel = blockIdx.y, c = threadIdx.x;
    const float* s = sel ? g_s2 : g_s1;
    float sv = s[b * 512 + c];
    ssq[c] = sv * sv;
    __syncthreads();
    float acc = 0.f;
#pragma unroll 8
    for (int k = 0; k < 512; ++k) acc += g_A[sel][k * 512 + c] * ssq[k];
    g_d[sel][b * 512 + c] = rsqrtf(acc + 1e-8f);
}

// srw[b][j][c] = convr_w[c][j] * fclscale * sr[b][c]
__global__ void srw_kernel(const float* __restrict__ wr) {
    int b = blockIdx.x, j = blockIdx.y, c = threadIdx.x;
    g_srw[((b * 3 + j) << 9) + c] = wr[c * 3 + j] * kFclScale * g_sr[b * 512 + c];
}

__global__ void rgb_init(float* __restrict__ rgb) {
    int idx = blockIdx.x * 256 + threadIdx.x;
#pragma unroll
    for (int i = 0; i < 8; ++i) rgb[idx + i * 24576] = 0.f;
}

__global__ void rgb_finalize(float* __restrict__ rgb, const float* __restrict__ biasr) {
    int idx = blockIdx.x * 256 + threadIdx.x;
#pragma unroll
    for (int i = 0; i < 8; ++i) {
        int k = idx + i * 24576;
        float v = rgb[k] + biasr[k % 3];
        rgb[k] = v >= 0.f ? v : 0.2f * v;
    }
}

// A1 = fp16(x * s1 * wscale)
__global__ void prep_a1(const float* __restrict__ x) {
    int idx = blockIdx.x * 256 + threadIdx.x;  // float4 units
    float4 v = ((const float4*)x)[idx];
    int b = idx >> 17, c4 = idx & 127;
    float4 s = ((const float4*)g_s1)[b * 128 + c4];
    __half2 h0 = __floats2half2_rn(v.x * s.x * WS9F, v.y * s.y * WS9F);
    __half2 h1 = __floats2half2_rn(v.z * s.z * WS9F, v.w * s.w * WS9F);
    ((__half2*)g_a1)[idx * 2] = h0;
    ((__half2*)g_a1)[idx * 2 + 1] = h1;
}

// wT[conv][t][cout][cin] = fp16(transpose(conv_w[t])), one conv per launch
__global__ void wprep_kernel(const float* __restrict__ w, int conv) {
    __shared__ float tile[32][33];
    int t = blockIdx.z;
    __half* dh = g_wh + (size_t)conv * 9 * 512 * 512;
    int ci0 = blockIdx.x * 32, co0 = blockIdx.y * 32;
    int tx = threadIdx.x & 31, ty = threadIdx.x >> 5;
#pragma unroll
    for (int r = 0; r < 4; ++r)
        tile[ty + r * 8][tx] = w[(((size_t)t * 512 + ci0 + ty + r * 8) << 9) + co0 + tx];
    __syncthreads();
#pragma unroll
    for (int r = 0; r < 4; ++r) {
        int co = co0 + ty + r * 8;
        dh[(((size_t)t * 512 + co) << 9) + ci0 + tx] = __float2half_rn(tile[tx][ty + r * 8]);
    }
}

// ---- HMMA implicit-GEMM conv: CTA 128px x 128cout, 8 warps (4M x 2N), K-stage 64 ----
#define ASTAGE 18432         // 128 rows * 144B
#define STAGE  36864         // A + B(128 rows * 144B)
#define SMEMSZ (3 * STAGE)   // 110592 -> 2 CTAs/SM

__global__ __launch_bounds__(256, 2)
void mma_conv_kernel(const __half* __restrict__ xin, int Hin, int Win,
                     const __half* __restrict__ wh,
                     int tapsBase, int tilesPerImg, int pxs, int pxm,
                     float* __restrict__ outf, __half* __restrict__ outh,
                     float* __restrict__ rgbAcc,
                     const float* __restrict__ dvec, const float* __restrict__ noise,
                     const float* __restrict__ snoise, const float* __restrict__ bias) {
    extern __shared__ __align__(16) char smem[];
    const uint32_t su = smem_u32(smem);
    const int tid = threadIdx.x, lane = tid & 31, wid = tid >> 5;
    const int sel = tapsBase + blockIdx.z;
    const int b = blockIdx.y / tilesPerImg;
    const int a0 = (blockIdx.y % tilesPerImg) * (128 >> pxs);
    const int cout0 = blockIdx.x * 128;
    const int m0 = (wid & 3) * 32, n0 = (wid >> 2) * 64;

    float acc[2][8][4];
#pragma unroll
    for (int i = 0; i < 2; ++i)
#pragma unroll
        for (int j = 0; j < 8; ++j)
#pragma unroll
            for (int k = 0; k < 4; ++k) acc[i][j][k] = 0.f;

    const int S = c_taps[sel].n * 8;

    auto load_stage = [&](int st, int p) {
        int t = st >> 3, ck = (st & 7) << 6;
        uint32_t base = su + p * STAGE;
        int dy = c_taps[sel].dy[t], dx = c_taps[sel].dx[t];
#pragma unroll
        for (int i = 0; i < 4; ++i) {   // A: 128 rows x 64 fp16
            int id = tid + i * 256;
            int r = id >> 3, seg = id & 7;
            int iy = a0 + (r >> pxs) + dy, ix = (r & pxm) + dx;
            bool ok = ((unsigned)iy < (unsigned)Hin) && ((unsigned)ix < (unsigned)Win);
            const void* src = xin + ((((size_t)b * Hin + (ok ? iy : 0)) * Win + (ok ? ix : 0)) << 9)
                              + ck + (seg << 3);
            cpa16(base + r * 144 + seg * 16, src, ok ? 16u : 0u);
        }
        const __half* wt = wh + (((size_t)(c_taps[sel].wi[t] * 512 + cout0)) << 9) + ck;
#pragma unroll
        for (int i = 0; i < 4; ++i) {   // B: 128 rows x 64 fp16
            int id = tid + i * 256;
            int row = id >> 3, seg = id & 7;
            cpa16(base + ASTAGE + row * 144 + seg * 16, wt + ((size_t)row << 9) + (seg << 3), 16u);
        }
    };

    auto compute = [&](int p) {
        uint32_t Ab = su + p * STAGE;
        uint32_t Bb = Ab + ASTAGE;
#pragma unroll
        for (int kk = 0; kk < 64; kk += 16) {
            uint32_t a[2][4];
#pragma unroll
            for (int mi = 0; mi < 2; ++mi) {
                uint32_t addr = Ab + (m0 + mi * 16 + (lane & 15)) * 144
                                + (kk + ((lane >> 4) << 3)) * 2;
                LDSM4(a[mi][0], a[mi][1], a[mi][2], a[mi][3], addr);
            }
            uint32_t bb[8][2];
#pragma unroll
            for (int ng = 0; ng < 4; ++ng) {
                int row = n0 + ng * 16 + (lane & 7) + ((lane >> 4) << 3);
                uint32_t addr = Bb + row * 144 + (kk + (((lane >> 3) & 1) << 3)) * 2;
                uint32_t r0, r1, r2, r3;
                LDSM4(r0, r1, r2, r3, addr);
                bb[ng * 2][0] = r0;     bb[ng * 2][1] = r1;
                bb[ng * 2 + 1][0] = r2; bb[ng * 2 + 1][1] = r3;
            }
#pragma unroll
            for (int mi = 0; mi < 2; ++mi)
#pragma unroll
                for (int ni = 0; ni < 8; ++ni)
                    mma16816(acc[mi][ni], a[mi], bb[ni]);
        }
    };

    // single-sync pipeline: wait(st) -> sync -> compute(st) -> load(st+2)
    load_stage(0, 0); CP_COMMIT();
    if (S > 1) { load_stage(1, 1); CP_COMMIT(); }
    for (int st = 0; st < S; ++st) {
        if (st + 1 < S) { CP_WAIT1(); } else { CP_WAIT0(); }
        __syncthreads();
        compute(st % 3);
        if (st + 2 < S) { load_stage(st + 2, (st + 2) % 3); CP_COMMIT(); }
    }

    // epilogue
    const int4 geo = c_geo[sel];
    const int quad = lane >> 2, tq = lane & 3;
    if (dvec) {
        float2 dv2[8], sn2[8], bi2[8];
#pragma unroll
        for (int ni = 0; ni < 8; ++ni) {
            int col = cout0 + n0 + ni * 8 + tq * 2;
            dv2[ni] = *(const float2*)(dvec + b * 512 + col);
            sn2[ni] = *(const float2*)(snoise + col);
            bi2[ni] = *(const float2*)(bias + col);
        }
        const float* sw = g_srw + ((size_t)(b * 3) << 9);
#pragma unroll
        for (int mi = 0; mi < 2; ++mi)
#pragma unroll
            for (int h = 0; h < 2; ++h) {
                int r = m0 + mi * 16 + quad + h * 8;
                int oy = (a0 + (r >> pxs)) * geo.x + geo.y;
                int ox = (r & pxm) * geo.z + geo.w;
                size_t pbase = (((size_t)b * 64 + oy) * 64 + ox) << 9;
                float nz = noise[(((size_t)b * 64 + oy) << 6) + ox];
                float r0 = 0.f, r1 = 0.f, r2 = 0.f;
#pragma unroll
                for (int ni = 0; ni < 8; ++ni) {
                    float c0 = acc[mi][ni][h * 2], c1 = acc[mi][ni][h * 2 + 1];
                    float2 v;
                    v.x = c0 * dv2[ni].x + sn2[ni].x * nz + bi2[ni].x;
                    v.y = c1 * dv2[ni].y + sn2[ni].y * nz + bi2[ni].y;
                    v.x = v.x >= 0.f ? v.x : 0.2f * v.x;
                    v.y = v.y >= 0.f ? v.y : 0.2f * v.y;
                    int col = cout0 + n0 + ni * 8 + tq * 2;
                    *(float2*)(outf + pbase + col) = v;
                    float2 w0 = *(const float2*)(sw + col);
                    float2 w1 = *(const float2*)(sw + 512 + col);
                    float2 w2 = *(const float2*)(sw + 1024 + col);
                    r0 += v.x * w0.x + v.y * w0.y;
                    r1 += v.x * w1.x + v.y * w1.y;
                    r2 += v.x * w2.x + v.y * w2.y;
                }
                // reduce over tq (4 consecutive lanes) and atomically accumulate rgb
                r0 += __shfl_xor_sync(0xffffffffu, r0, 1);
                r0 += __shfl_xor_sync(0xffffffffu, r0, 2);
                r1 += __shfl_xor_sync(0xffffffffu, r1, 1);
                r1 += __shfl_xor_sync(0xffffffffu, r1, 2);
                r2 += __shfl_xor_sync(0xffffffffu, r2, 1);
                r2 += __shfl_xor_sync(0xffffffffu, r2, 2);
                if (tq == 0) {
                    size_t pix = ((size_t)b * 64 + oy) * 64 + ox;
                    atomicAdd(rgbAcc + pix * 3 + 0, r0);
                    atomicAdd(rgbAcc + pix * 3 + 1, r1);
                    atomicAdd(rgbAcc + pix * 3 + 2, r2);
                }
            }
    } else {
#pragma unroll
        for (int mi = 0; mi < 2; ++mi)
#pragma unroll
            for (int h = 0; h < 2; ++h) {
                int r = m0 + mi * 16 + quad + h * 8;
                int oy = (a0 + (r >> pxs)) * geo.x + geo.y;
                int ox = (r & pxm) * geo.z + geo.w;
                size_t pbase = (((size_t)b * 64 + oy) * 64 + ox) << 9;
#pragma unroll
                for (int ni = 0; ni < 8; ++ni) {
                    __half2 v = __floats2half2_rn(acc[mi][ni][h * 2], acc[mi][ni][h * 2 + 1]);
                    *(__half2*)(outh + pbase + cout0 + n0 + ni * 8 + tq * 2) = v;
                }
            }
    }
}

// ---- blur (fp16 in, branch-free x) + demod1 + noise + bias + lrelu -> fp16 ----
__global__ void blur_kernel(const __half* __restrict__ ydc, __half* __restrict__ xout,
                            const float* __restrict__ noise, const float* __restrict__ snoise,
                            const float* __restrict__ bias) {
    const int cg = threadIdx.x & 127, c = cg * 4;
    const int xi = (blockIdx.x % 32) * 2 + (threadIdx.x >> 7);
    const int b = blockIdx.x / 32;
    const float F[4] = {0.25f, 0.75f, 0.75f, 0.25f};

    // precompute clamped x offsets + edge-zeroed weights (branch-free inner loop)
    int xoff[4]; float wx[4];
#pragma unroll
    for (int u = 0; u < 4; ++u) {
        int xx = xi + u - 1;
        wx[u] = (xx >= 0 && xx < 64) ? F[u] : 0.f;
        int xc = xx < 0 ? 0 : (xx > 63 ? 63 : xx);
        xoff[u] = xc * 512;
    }

    float4 dvv = *(const float4*)(&g_d[0][b * 512 + c]);
    float4 snv = *(const float4*)(snoise + c);
    float4 biv = *(const float4*)(bias + c);
    float4 s2v = *(const float4*)(&g_s2[b * 512 + c]);

    auto hrow = [&](int v) -> float4 {
        float4 r = make_float4(0.f, 0.f, 0.f, 0.f);
        if ((unsigned)v >= 64u) return r;
        const __half* rb = ydc + (((size_t)(b * 64 + v)) << 15) + c;
#pragma unroll
        for (int u = 0; u < 4; ++u) {
            const __half2* p = (const __half2*)(rb + xoff[u]);
            float2 t0 = __half22float2(p[0]);
            float2 t1 = __half22float2(p[1]);
            r.x += wx[u] * t0.x; r.y += wx[u] * t0.y;
            r.z += wx[u] * t1.x; r.w += wx[u] * t1.y;
        }
        return r;
    };

    float4 h0 = make_float4(0.f, 0.f, 0.f, 0.f);
    float4 h1 = hrow(0), h2 = hrow(1);
    for (int y = 0; y < 64; ++y) {
        float4 h3 = hrow(y + 2);
        float4 o;
        o.x = 0.25f * h0.x + 0.75f * h1.x + 0.75f * h2.x + 0.25f * h3.x;
        o.y = 0.25f * h0.y + 0.75f * h1.y + 0.75f * h2.y + 0.25f * h3.y;
        o.z = 0.25f * h0.z + 0.75f * h1.z + 0.75f * h2.z + 0.25f * h3.z;
        o.w = 0.25f * h0.w + 0.75f * h1.w + 0.75f * h2.w + 0.25f * h3.w;
        float nz = noise[((size_t)b * 64 + y) * 64 + xi];
        float4 v;
        v.x = o.x * dvv.x + snv.x * nz + biv.x;
        v.y = o.y * dvv.y + snv.y * nz + biv.y;
        v.z = o.z * dvv.z + snv.z * nz + biv.z;
        v.w = o.w * dvv.w + snv.w * nz + biv.w;
        v.x = v.x >= 0.f ? v.x : 0.2f * v.x;
        v.y = v.y >= 0.f ? v.y : 0.2f * v.y;
        v.z = v.z >= 0.f ? v.z : 0.2f * v.z;
        v.w = v.w >= 0.f ? v.w : 0.2f * v.w;
        size_t off = (((size_t)b * 64 + y) * 64 + xi) * 512 + c;
        __half2 p0 = __floats2half2_rn(v.x * s2v.x * WS9F, v.y * s2v.y * WS9F);
        __half2 p1 = __floats2half2_rn(v.z * s2v.z * WS9F, v.w * s2v.w * WS9F);
        ((__half2*)(xout + off))[0] = p0;
        ((__half2*)(xout + off))[1] = p1;
        h0 = h1; h1 = h2; h2 = h3;
    }
}

// ---- launch ----
extern "C" void kernel_launch(void* const* d_in, const int* in_sizes, int n_in,
                              void* d_out, int out_size) {
    const float* x       = (const float*)d_in[0];
    const float* w       = (const float*)d_in[1];
    const float* noise1  = (const float*)d_in[2];
    const float* noise2  = (const float*)d_in[3];
    const float* fcl1_w  = (const float*)d_in[4];
    const float* fcl1_b  = (const float*)d_in[5];
    const float* conv1_w = (const float*)d_in[6];
    const float* sn1     = (const float*)d_in[7];
    const float* bias1   = (const float*)d_in[8];
    const float* fcl2_w  = (const float*)d_in[9];
    const float* fcl2_b  = (const float*)d_in[10];
    const float* conv2_w = (const float*)d_in[11];
    const float* sn2     = (const float*)d_in[12];
    const float* bias2   = (const float*)d_in[13];
    const float* fclr_w  = (const float*)d_in[14];
    const float* fclr_b  = (const float*)d_in[15];
    const float* convr_w = (const float*)d_in[16];
    const float* biasr   = (const float*)d_in[17];

    float* x2out  = (float*)d_out;
    float* rgbout = x2out + (size_t)B_ * 64 * 64 * 512;

    float *s1, *s2, *sr, *dd;
    __half *ydc, *a1, *a2, *wh;
    cudaGetSymbolAddress((void**)&s1, g_s1);
    cudaGetSymbolAddress((void**)&s2, g_s2);
    cudaGetSymbolAddress((void**)&sr, g_sr);
    cudaGetSymbolAddress((void**)&dd, g_d);
    cudaGetSymbolAddress((void**)&ydc, g_ydc);
    cudaGetSymbolAddress((void**)&a1, g_a1);
    cudaGetSymbolAddress((void**)&a2, g_a2);
    cudaGetSymbolAddress((void**)&wh, g_wh);
    float* d2 = dd + B_ * 512;

    // one-time resources (created on the first, non-captured correctness call)
    static cudaStream_t s_aux1 = nullptr, s_aux2 = nullptr;
    static cudaEvent_t evF = nullptr, evW0 = nullptr, evFCL = nullptr, evA2 = nullptr;
    static bool attrSet = false;
    if (!s_aux1) {
        cudaStreamCreateWithFlags(&s_aux1, cudaStreamNonBlocking);
        cudaStreamCreateWithFlags(&s_aux2, cudaStreamNonBlocking);
        cudaEventCreateWithFlags(&evF, cudaEventDisableTiming);
        cudaEventCreateWithFlags(&evW0, cudaEventDisableTiming);
        cudaEventCreateWithFlags(&evFCL, cudaEventDisableTiming);
        cudaEventCreateWithFlags(&evA2, cudaEventDisableTiming);
    }
    if (!attrSet) {
        cudaFuncSetAttribute(mma_conv_kernel, cudaFuncAttributeMaxDynamicSharedMemorySize, SMEMSZ);
        attrSet = true;
    }

    // fork both aux streams at entry
    cudaEventRecord(evF, 0);
    cudaStreamWaitEvent(s_aux1, evF, 0);
    cudaStreamWaitEvent(s_aux2, evF, 0);

    // aux1: conv1 weight transpose (no style dependency) -> needed before deconv
    wprep_kernel<<<dim3(16, 16, 9), 256, 0, s_aux1>>>(conv1_w, 0);
    cudaEventRecord(evW0, s_aux1);

    // aux2: conv2/torgb prep (independent parts first)
    rgb_init<<<96, 256, 0, s_aux2>>>(rgbout);
    a_kernel<<<dim3(512, 2), 512, 0, s_aux2>>>(conv1_w, conv2_w);
    wprep_kernel<<<dim3(16, 16, 9), 256, 0, s_aux2>>>(conv2_w, 1);

    // main: styles
    fcl3_kernel<<<dim3(B_, 3), 512>>>(w, fcl1_w, fcl1_b, s1, fcl2_w, fcl2_b, s2,
                                      fclr_w, fclr_b, sr);
    cudaEventRecord(evFCL, 0);

    // aux2 tail: style-dependent prep
    cudaStreamWaitEvent(s_aux2, evFCL, 0);
    d_kernel<<<dim3(B_, 2), 512, 0, s_aux2>>>();
    srw_kernel<<<dim3(B_, 3), 512, 0, s_aux2>>>(convr_w);
    cudaEventRecord(evA2, s_aux2);

    // main chain: a1 prep -> deconv -> blur
    prep_a1<<<8192, 256>>>(x);
    cudaStreamWaitEvent(0, evW0, 0);

    // deconv: 4 parity classes in ONE launch (grid.z = class), M=128 input-px tiles
    mma_conv_kernel<<<dim3(4, B_ * 8, 4), 256, SMEMSZ>>>(
        a1, 32, 32, wh, /*tapsBase=*/0, /*tilesPerImg=*/8, /*pxs=*/5, /*pxm=*/31,
        nullptr, ydc, nullptr, nullptr, nullptr, nullptr, nullptr);

    blur_kernel<<<B_ * 32, 256>>>(ydc, a2, noise1, sn1, bias1);

    // join aux2 prep (incl. rgb_init) before conv2
    cudaStreamWaitEvent(0, evA2, 0);

    // conv2: 3x3 SAME, fused demod/noise/bias/lrelu + fused toRGB partials -> d_out
    mma_conv_kernel<<<dim3(4, B_ * 32, 1), 256, SMEMSZ>>>(
        a2, 64, 64, wh + (size_t)9 * 512 * 512, /*tapsBase=*/4, /*tilesPerImg=*/32,
        /*pxs=*/6, /*pxm=*/63,
        x2out, nullptr, rgbout, d2, noise2, sn2, bias2);

    rgb_finalize<<<96, 256>>>(rgbout, biasr);
}